// round 10
// baseline (speedup 1.0000x reference)
#include <cuda_runtime.h>
#include <math.h>

#define SEQ 4096
#define DM  768
#define NH  12
#define DH  64
#define FF  3072
#define NE  7
#define WIN 256
#define CAP 4096

// ---------------- scratch (static device globals; no allocation) ----------------
__device__ float g_q[NH * SEQ * DH];
__device__ float g_k[NH * SEQ * DH];
__device__ float g_v[NH * SEQ * DH];
__device__ float g_attno[SEQ * DM];
__device__ float g_tmp[SEQ * DM];
__device__ float g_x1[SEQ * DM];
__device__ float g_moe[SEQ * DM];
__device__ float g_h[NE * CAP * FF];     // 352 MB
__device__ float g_eo[NE * CAP * DM];    // 88 MB
__device__ int   g_cnt[NE];
__device__ int   g_tok[NE * CAP];
__device__ float g_wl[NE * CAP];
__device__ int   g_pos[SEQ * 2];

// ---------------- reset ----------------
__global__ void reset_kernel() {
    if (threadIdx.x < NE) g_cnt[threadIdx.x] = 0;
}

// ======================================================================
// fp32 SIMT GEMM (kept for the gating-critical path: QKV, Wo)
// ======================================================================
#define BM 128
#define BN 64
#define BK 16

__global__ __launch_bounds__(256) void gemm_kernel(
    const float* __restrict__ A, const float* __restrict__ B,
    const float* __restrict__ bias, float* __restrict__ C,
    int M, int N, int K, const float* __restrict__ residual,
    float scale, int mode)
{
    __shared__ float As[BK][BM];
    __shared__ float Bs[BK][BN];
    int tid = threadIdx.x;
    int m0 = blockIdx.y * BM;
    int n0 = blockIdx.x * BN;
    int rg = tid >> 4;
    int cg = tid & 15;
    int ar = tid >> 2;
    int ac = (tid & 3) << 2;
    int br = tid >> 4;
    int bc = (tid & 15) << 2;

    float acc[8][4];
#pragma unroll
    for (int i = 0; i < 8; i++)
#pragma unroll
        for (int j = 0; j < 4; j++) acc[i][j] = 0.f;

    for (int k0 = 0; k0 < K; k0 += BK) {
#pragma unroll
        for (int it = 0; it < 2; it++) {
            int r = ar + it * 64;
            float4 av = *(const float4*)&A[(size_t)(m0 + r) * K + k0 + ac];
            As[ac + 0][r] = av.x;
            As[ac + 1][r] = av.y;
            As[ac + 2][r] = av.z;
            As[ac + 3][r] = av.w;
        }
        float4 bv = *(const float4*)&B[(size_t)(k0 + br) * N + n0 + bc];
        *(float4*)&Bs[br][bc] = bv;
        __syncthreads();
#pragma unroll
        for (int k = 0; k < BK; k++) {
            float4 a0 = *(const float4*)&As[k][rg * 8];
            float4 a1 = *(const float4*)&As[k][rg * 8 + 4];
            float4 b0 = *(const float4*)&Bs[k][cg * 4];
            float a[8] = {a0.x, a0.y, a0.z, a0.w, a1.x, a1.y, a1.z, a1.w};
            float b[4] = {b0.x, b0.y, b0.z, b0.w};
#pragma unroll
            for (int i = 0; i < 8; i++)
#pragma unroll
                for (int j = 0; j < 4; j++) acc[i][j] += a[i] * b[j];
        }
        __syncthreads();
    }

#pragma unroll
    for (int i = 0; i < 8; i++) {
        int row = m0 + rg * 8 + i;
#pragma unroll
        for (int j = 0; j < 4; j++) {
            int col = n0 + cg * 4 + j;
            float v = acc[i][j] + bias[col];
            if (mode == 0) {
                C[(size_t)row * N + col] = v;
            } else if (mode == 1) {
                C[((size_t)(col >> 6) * M + row) * 64 + (col & 63)] = v * scale;
            } else {
                C[(size_t)row * N + col] = v + residual[(size_t)row * N + col];
            }
        }
    }
}

// ======================================================================
// tf32 tensor-core GEMM machinery (mma.sync.m16n8k8)
// BM=128, BN=64, BK=16, 256 threads = 8 warps in 4x2, warp tile 32x32.
// ======================================================================
#define APADM 136   // BM + 8 : conflict-free fragment loads
#define APADN 72    // BN + 8

__device__ __forceinline__ unsigned f2tf(float f) {
    unsigned u;
    asm("cvt.rna.tf32.f32 %0, %1;" : "=r"(u) : "f"(f));
    return u;
}

__device__ __forceinline__ void mma_tf32(float* c, const unsigned* a, const unsigned* b) {
    asm volatile(
        "mma.sync.aligned.m16n8k8.row.col.f32.tf32.tf32.f32 "
        "{%0,%1,%2,%3}, {%4,%5,%6,%7}, {%8,%9}, {%0,%1,%2,%3};"
        : "+f"(c[0]), "+f"(c[1]), "+f"(c[2]), "+f"(c[3])
        : "r"(a[0]), "r"(a[1]), "r"(a[2]), "r"(a[3]),
          "r"(b[0]), "r"(b[1]));
}

// shared mainloop body: fills acc[2][4][4] for this block/warp
// A_loader: lambda-free — implemented via macro parameters in each kernel
#define MMA_DECLS()                                                        \
    __shared__ unsigned As[BK][APADM];                                     \
    __shared__ unsigned Bs[BK][APADN];                                     \
    int tid = threadIdx.x;                                                 \
    int ar = tid >> 2, ac = (tid & 3) << 2;                                \
    int br = tid >> 4, bc = (tid & 15) << 2;                               \
    int w = tid >> 5, lane = tid & 31;                                     \
    int m0w = (w >> 1) * 32, n0w = (w & 1) * 32;                           \
    int g = lane >> 2, t = lane & 3;                                       \
    float acc[2][4][4];                                                    \
    _Pragma("unroll")                                                      \
    for (int mi = 0; mi < 2; mi++)                                         \
        _Pragma("unroll")                                                  \
        for (int ni = 0; ni < 4; ni++)                                     \
            _Pragma("unroll")                                              \
            for (int j = 0; j < 4; j++) acc[mi][ni][j] = 0.f;

#define MMA_COMPUTE()                                                      \
    __syncthreads();                                                       \
    _Pragma("unroll")                                                      \
    for (int kk = 0; kk < BK; kk += 8) {                                   \
        unsigned afr[2][4], bfr[4][2];                                     \
        _Pragma("unroll")                                                  \
        for (int mi = 0; mi < 2; mi++) {                                   \
            int mb = m0w + mi * 16 + g;                                    \
            afr[mi][0] = As[kk + t][mb];                                   \
            afr[mi][1] = As[kk + t][mb + 8];                               \
            afr[mi][2] = As[kk + t + 4][mb];                               \
            afr[mi][3] = As[kk + t + 4][mb + 8];                           \
        }                                                                  \
        _Pragma("unroll")                                                  \
        for (int ni = 0; ni < 4; ni++) {                                   \
            int nb = n0w + ni * 8 + g;                                     \
            bfr[ni][0] = Bs[kk + t][nb];                                   \
            bfr[ni][1] = Bs[kk + t + 4][nb];                               \
        }                                                                  \
        _Pragma("unroll")                                                  \
        for (int mi = 0; mi < 2; mi++)                                     \
            _Pragma("unroll")                                              \
            for (int ni = 0; ni < 4; ni++)                                 \
                mma_tf32(acc[mi][ni], afr[mi], bfr[ni]);                   \
    }                                                                      \
    __syncthreads();

// ---------------- MoE GEMM 1 (tf32): gather + GELU ----------------
__global__ __launch_bounds__(256) void mma_moe_gemm1(
    const float* __restrict__ X, const float* __restrict__ W1,
    const float* __restrict__ b1)
{
    int e = blockIdx.z;
    int M = g_cnt[e];
    int m0 = blockIdx.y * BM;
    if (m0 >= M) return;
    const float* B = W1 + (size_t)e * DM * FF;
    const float* bias = b1 + (size_t)e * FF;
    float* C = g_h + (size_t)e * CAP * FF;
    const int* tl = g_tok + e * CAP;
    int n0 = blockIdx.x * BN;

    MMA_DECLS();

    for (int k0 = 0; k0 < DM; k0 += BK) {
#pragma unroll
        for (int it = 0; it < 2; it++) {
            int r = ar + it * 64;
            int grow = m0 + r;
            float4 av = make_float4(0.f, 0.f, 0.f, 0.f);
            if (grow < M) {
                int trow = tl[grow];
                av = *(const float4*)&X[(size_t)trow * DM + k0 + ac];
            }
            As[ac + 0][r] = f2tf(av.x);
            As[ac + 1][r] = f2tf(av.y);
            As[ac + 2][r] = f2tf(av.z);
            As[ac + 3][r] = f2tf(av.w);
        }
        {
            float4 bv = *(const float4*)&B[(size_t)(k0 + br) * FF + n0 + bc];
            Bs[br][bc + 0] = f2tf(bv.x);
            Bs[br][bc + 1] = f2tf(bv.y);
            Bs[br][bc + 2] = f2tf(bv.z);
            Bs[br][bc + 3] = f2tf(bv.w);
        }
        MMA_COMPUTE();
    }

#pragma unroll
    for (int mi = 0; mi < 2; mi++) {
#pragma unroll
        for (int ni = 0; ni < 4; ni++) {
            int col = n0 + n0w + ni * 8 + 2 * t;
            float bv0 = bias[col], bv1 = bias[col + 1];
#pragma unroll
            for (int half = 0; half < 2; half++) {
                int row = m0 + m0w + mi * 16 + g + half * 8;
                if (row >= M) continue;
                float v0 = acc[mi][ni][half * 2 + 0] + bv0;
                float v1 = acc[mi][ni][half * 2 + 1] + bv1;
                v0 = 0.5f * v0 * (1.f + erff(v0 * 0.70710678118654752f));
                v1 = 0.5f * v1 * (1.f + erff(v1 * 0.70710678118654752f));
                C[(size_t)row * FF + col]     = v0;
                C[(size_t)row * FF + col + 1] = v1;
            }
        }
    }
}

// ---------------- MoE GEMM 2 (tf32): * gate weight ----------------
__global__ __launch_bounds__(256) void mma_moe_gemm2(
    const float* __restrict__ W2, const float* __restrict__ b2)
{
    int e = blockIdx.z;
    int M = g_cnt[e];
    int m0 = blockIdx.y * BM;
    if (m0 >= M) return;
    const float* A = g_h + (size_t)e * CAP * FF;
    const float* B = W2 + (size_t)e * FF * DM;
    const float* bias = b2 + (size_t)e * DM;
    const float* wl = g_wl + e * CAP;
    float* C = g_eo + (size_t)e * CAP * DM;
    int n0 = blockIdx.x * BN;

    MMA_DECLS();

    for (int k0 = 0; k0 < FF; k0 += BK) {
#pragma unroll
        for (int it = 0; it < 2; it++) {
            int r = ar + it * 64;
            int grow = m0 + r;
            float4 av = make_float4(0.f, 0.f, 0.f, 0.f);
            if (grow < M) av = *(const float4*)&A[(size_t)grow * FF + k0 + ac];
            As[ac + 0][r] = f2tf(av.x);
            As[ac + 1][r] = f2tf(av.y);
            As[ac + 2][r] = f2tf(av.z);
            As[ac + 3][r] = f2tf(av.w);
        }
        {
            float4 bv = *(const float4*)&B[(size_t)(k0 + br) * DM + n0 + bc];
            Bs[br][bc + 0] = f2tf(bv.x);
            Bs[br][bc + 1] = f2tf(bv.y);
            Bs[br][bc + 2] = f2tf(bv.z);
            Bs[br][bc + 3] = f2tf(bv.w);
        }
        MMA_COMPUTE();
    }

#pragma unroll
    for (int mi = 0; mi < 2; mi++) {
#pragma unroll
        for (int ni = 0; ni < 4; ni++) {
            int col = n0 + n0w + ni * 8 + 2 * t;
            float bv0 = bias[col], bv1 = bias[col + 1];
#pragma unroll
            for (int half = 0; half < 2; half++) {
                int row = m0 + m0w + mi * 16 + g + half * 8;
                if (row >= M) continue;
                float wv = wl[row];
                C[(size_t)row * DM + col]     = (acc[mi][ni][half * 2 + 0] + bv0) * wv;
                C[(size_t)row * DM + col + 1] = (acc[mi][ni][half * 2 + 1] + bv1) * wv;
            }
        }
    }
}

// ---------------- Wd GEMM (tf32): + bias + residual ----------------
__global__ __launch_bounds__(256) void mma_gemm_res(
    const float* __restrict__ A, const float* __restrict__ B,
    const float* __restrict__ bias, float* __restrict__ C,
    const float* __restrict__ R, int M, int N, int K)
{
    int m0 = blockIdx.y * BM;
    int n0 = blockIdx.x * BN;

    MMA_DECLS();

    for (int k0 = 0; k0 < K; k0 += BK) {
#pragma unroll
        for (int it = 0; it < 2; it++) {
            int r = ar + it * 64;
            float4 av = *(const float4*)&A[(size_t)(m0 + r) * K + k0 + ac];
            As[ac + 0][r] = f2tf(av.x);
            As[ac + 1][r] = f2tf(av.y);
            As[ac + 2][r] = f2tf(av.z);
            As[ac + 3][r] = f2tf(av.w);
        }
        {
            float4 bv = *(const float4*)&B[(size_t)(k0 + br) * N + n0 + bc];
            Bs[br][bc + 0] = f2tf(bv.x);
            Bs[br][bc + 1] = f2tf(bv.y);
            Bs[br][bc + 2] = f2tf(bv.z);
            Bs[br][bc + 3] = f2tf(bv.w);
        }
        MMA_COMPUTE();
    }

#pragma unroll
    for (int mi = 0; mi < 2; mi++) {
#pragma unroll
        for (int ni = 0; ni < 4; ni++) {
            int col = n0 + n0w + ni * 8 + 2 * t;
            float bv0 = bias[col], bv1 = bias[col + 1];
#pragma unroll
            for (int half = 0; half < 2; half++) {
                int row = m0 + m0w + mi * 16 + g + half * 8;
                size_t idx = (size_t)row * N + col;
                C[idx]     = acc[mi][ni][half * 2 + 0] + bv0 + R[idx];
                C[idx + 1] = acc[mi][ni][half * 2 + 1] + bv1 + R[idx + 1];
            }
        }
    }
}

// ---------------- fused sliding-window attention ----------------
#define APAD 68
__global__ __launch_bounds__(256) void attn_kernel(float* __restrict__ out)
{
    __shared__ float Qs[64][APAD];
    __shared__ float Ks[32][APAD];
    __shared__ float Vs[32][APAD];
    __shared__ float Ss[64][33];
    __shared__ float mS[64], lS[64], cS[64];

    int h = blockIdx.y;
    int q0 = blockIdx.x * 64;
    int tid = threadIdx.x;
    int q = tid & 63;
    int kg = tid >> 6;
    int dp = tid >> 6;

    const float* qhead = g_q + (size_t)h * SEQ * DH;
    const float* khead = g_k + (size_t)h * SEQ * DH;
    const float* vhead = g_v + (size_t)h * SEQ * DH;

#pragma unroll
    for (int i = 0; i < 4; i++) {
        int idx = tid + i * 256;
        int r = idx >> 4;
        int c = (idx & 15) << 2;
        float4 v = *(const float4*)&qhead[(size_t)(q0 + r) * DH + c];
        *(float4*)&Qs[r][c] = v;
    }
    if (tid < 64) { mS[tid] = -1e9f; lS[tid] = 0.f; }

    float acc[16];
#pragma unroll
    for (int i = 0; i < 16; i++) acc[i] = 0.f;
    __syncthreads();

    for (int kt = 0; kt < 18; kt++) {
        int kbase = q0 - 256 + kt * 32;
        if (kbase + 31 < 0 || kbase >= SEQ) continue;

#pragma unroll
        for (int i = 0; i < 2; i++) {
            int idx = tid + i * 256;
            int r = idx >> 4;
            int c = (idx & 15) << 2;
            int kpos = kbase + r;
            float4 kv = make_float4(0.f, 0.f, 0.f, 0.f);
            float4 vv = kv;
            if (kpos >= 0 && kpos < SEQ) {
                kv = *(const float4*)&khead[(size_t)kpos * DH + c];
                vv = *(const float4*)&vhead[(size_t)kpos * DH + c];
            }
            *(float4*)&Ks[r][c] = kv;
            *(float4*)&Vs[r][c] = vv;
        }
        __syncthreads();

        float s[8];
#pragma unroll
        for (int j = 0; j < 8; j++) s[j] = 0.f;
#pragma unroll
        for (int d = 0; d < 64; d += 4) {
            float4 q4 = *(const float4*)&Qs[q][d];
#pragma unroll
            for (int j = 0; j < 8; j++) {
                float4 k4 = *(const float4*)&Ks[kg * 8 + j][d];
                s[j] += q4.x * k4.x + q4.y * k4.y + q4.z * k4.z + q4.w * k4.w;
            }
        }
        int qpos = q0 + q;
#pragma unroll
        for (int j = 0; j < 8; j++) {
            int kpos = kbase + kg * 8 + j;
            bool valid = (kpos >= 0) && (kpos < SEQ) &&
                         (kpos >= qpos - WIN) && (kpos <= qpos + WIN);
            Ss[q][kg * 8 + j] = valid ? s[j] : -1e9f;
        }
        __syncthreads();

        if (tid < 64) {
            int r = tid;
            float mold = mS[r];
            float tmax = -1e9f;
#pragma unroll
            for (int kk = 0; kk < 32; kk++) tmax = fmaxf(tmax, Ss[r][kk]);
            float mnew = fmaxf(mold, tmax);
            float corr = __expf(mold - mnew);
            float sum = 0.f;
#pragma unroll
            for (int kk = 0; kk < 32; kk++) {
                float p = __expf(Ss[r][kk] - mnew);
                Ss[r][kk] = p;
                sum += p;
            }
            lS[r] = lS[r] * corr + sum;
            mS[r] = mnew;
            cS[r] = corr;
        }
        __syncthreads();

        float corr = cS[q];
#pragma unroll
        for (int i = 0; i < 16; i++) acc[i] *= corr;
#pragma unroll
        for (int kk = 0; kk < 32; kk++) {
            float p = Ss[q][kk];
#pragma unroll
            for (int i4 = 0; i4 < 4; i4++) {
                float4 v4 = *(const float4*)&Vs[kk][dp * 16 + i4 * 4];
                acc[i4 * 4 + 0] += p * v4.x;
                acc[i4 * 4 + 1] += p * v4.y;
                acc[i4 * 4 + 2] += p * v4.z;
                acc[i4 * 4 + 3] += p * v4.w;
            }
        }
        __syncthreads();
    }

    float inv = 1.f / lS[q];
    float* o = out + (size_t)(q0 + q) * DM + h * DH + dp * 16;
#pragma unroll
    for (int i4 = 0; i4 < 4; i4++) {
        float4 v;
        v.x = acc[i4 * 4 + 0] * inv;
        v.y = acc[i4 * 4 + 1] * inv;
        v.z = acc[i4 * 4 + 2] * inv;
        v.w = acc[i4 * 4 + 3] * inv;
        *(float4*)&o[i4 * 4] = v;
    }
}

// ---------------- layer norm (row-wise) ----------------
__global__ __launch_bounds__(256) void ln_kernel(
    const float* __restrict__ in, const float* __restrict__ g,
    const float* __restrict__ b, float* __restrict__ out)
{
    __shared__ float rs[8], rs2[8];
    int row = blockIdx.x;
    int tid = threadIdx.x;
    const float* x = in + (size_t)row * DM;
    float vals[3];
    float s = 0.f, s2 = 0.f;
#pragma unroll
    for (int i = 0; i < 3; i++) {
        float v = x[tid + i * 256];
        vals[i] = v;
        s += v;
        s2 += v * v;
    }
    int lane = tid & 31, w = tid >> 5;
#pragma unroll
    for (int o = 16; o; o >>= 1) {
        s += __shfl_down_sync(0xffffffffu, s, o);
        s2 += __shfl_down_sync(0xffffffffu, s2, o);
    }
    if (lane == 0) { rs[w] = s; rs2[w] = s2; }
    __syncthreads();
    if (tid == 0) {
        float a = 0.f, c = 0.f;
#pragma unroll
        for (int i = 0; i < 8; i++) { a += rs[i]; c += rs2[i]; }
        rs[0] = a;
        rs2[0] = c;
    }
    __syncthreads();
    float mean = rs[0] * (1.f / DM);
    float var = rs2[0] * (1.f / DM) - mean * mean;
    float rstd = rsqrtf(var + 1e-5f);
    float* o = out + (size_t)row * DM;
#pragma unroll
    for (int i = 0; i < 3; i++) {
        int col = tid + i * 256;
        o[col] = (vals[i] - mean) * rstd * g[col] + b[col];
    }
}

// ---------------- gating: logits, top-2, softmax, expert lists ----------------
__global__ __launch_bounds__(256) void gating_kernel(
    const float* __restrict__ x1, const float* __restrict__ gW,
    const float* __restrict__ gb, float* __restrict__ gate_out)
{
    __shared__ float xs[DM];
    __shared__ float lg[8];
    int row = blockIdx.x;
    int tid = threadIdx.x;
    for (int i = tid; i < DM; i += 256) xs[i] = x1[(size_t)row * DM + i];
    __syncthreads();
    int w = tid >> 5, lane = tid & 31;
    if (w < NE) {
        float p = 0.f;
        for (int d = lane; d < DM; d += 32) p += xs[d] * gW[d * NE + w];
#pragma unroll
        for (int o = 16; o; o >>= 1) p += __shfl_down_sync(0xffffffffu, p, o);
        if (lane == 0) lg[w] = p + gb[w];
    }
    __syncthreads();
    if (tid == 0) {
        int e1 = 0;
        float v1 = lg[0];
        for (int e = 1; e < NE; e++)
            if (lg[e] > v1) { v1 = lg[e]; e1 = e; }
        int e2 = -1;
        float v2 = -1e30f;
        for (int e = 0; e < NE; e++) {
            if (e == e1) continue;
            if (lg[e] > v2) { v2 = lg[e]; e2 = e; }
        }
        float z = expf(v2 - v1);
        float w1 = 1.f / (1.f + z);
        float w2 = z / (1.f + z);
        float* go = gate_out + (size_t)row * NE;
#pragma unroll
        for (int e = 0; e < NE; e++) go[e] = 0.f;
        go[e1] = w1;
        go[e2] = w2;
        int s1 = atomicAdd(&g_cnt[e1], 1);
        g_tok[e1 * CAP + s1] = row;
        g_wl[e1 * CAP + s1] = w1;
        g_pos[row * 2 + 0] = e1 * CAP + s1;
        int s2 = atomicAdd(&g_cnt[e2], 1);
        g_tok[e2 * CAP + s2] = row;
        g_wl[e2 * CAP + s2] = w2;
        g_pos[row * 2 + 1] = e2 * CAP + s2;
    }
}

// ---------------- combine two expert outputs per token ----------------
__global__ __launch_bounds__(192) void combine_kernel()
{
    int t = blockIdx.x;
    int p0 = g_pos[t * 2 + 0];
    int p1 = g_pos[t * 2 + 1];
    const float* a = g_eo + (size_t)p0 * DM;
    const float* b = g_eo + (size_t)p1 * DM;
    float* o = g_moe + (size_t)t * DM;
    int i = threadIdx.x * 4;
    float4 av = *(const float4*)&a[i];
    float4 bv = *(const float4*)&b[i];
    float4 v;
    v.x = av.x + bv.x;
    v.y = av.y + bv.y;
    v.z = av.z + bv.z;
    v.w = av.w + bv.w;
    *(float4*)&o[i] = v;
}

// ---------------- launch ----------------
extern "C" void kernel_launch(void* const* d_in, const int* in_sizes, int n_in,
                              void* d_out, int out_size)
{
    (void)in_sizes; (void)n_in; (void)out_size;
    const float* x     = (const float*)d_in[0];
    const float* Wq    = (const float*)d_in[1];
    const float* bq    = (const float*)d_in[2];
    const float* Wk    = (const float*)d_in[3];
    const float* bk    = (const float*)d_in[4];
    const float* Wv    = (const float*)d_in[5];
    const float* bv    = (const float*)d_in[6];
    const float* Wo    = (const float*)d_in[7];
    const float* bo    = (const float*)d_in[8];
    const float* ln1g  = (const float*)d_in[9];
    const float* ln1b  = (const float*)d_in[10];
    const float* gateW = (const float*)d_in[11];
    const float* gateb = (const float*)d_in[12];
    const float* W1e   = (const float*)d_in[13];
    const float* b1e   = (const float*)d_in[14];
    const float* W2e   = (const float*)d_in[15];
    const float* b2e   = (const float*)d_in[16];
    const float* Wd    = (const float*)d_in[17];
    const float* bd    = (const float*)d_in[18];
    const float* ln2g  = (const float*)d_in[19];
    const float* ln2b  = (const float*)d_in[20];

    float* out = (float*)d_out;
    float* gate_out = out + (size_t)SEQ * DM;

    float *pq, *pk, *pv, *pattno, *ptmp, *px1, *pmoe;
    cudaGetSymbolAddress((void**)&pq, g_q);
    cudaGetSymbolAddress((void**)&pk, g_k);
    cudaGetSymbolAddress((void**)&pv, g_v);
    cudaGetSymbolAddress((void**)&pattno, g_attno);
    cudaGetSymbolAddress((void**)&ptmp, g_tmp);
    cudaGetSymbolAddress((void**)&px1, g_x1);
    cudaGetSymbolAddress((void**)&pmoe, g_moe);

    dim3 gemm_grid(DM / BN, SEQ / BM);   // (12, 32)

    reset_kernel<<<1, 32>>>();

    // QKV projections (fp32 — gating-critical path; q pre-scaled by 1/sqrt(64))
    gemm_kernel<<<gemm_grid, 256>>>(x, Wq, bq, pq, SEQ, DM, DM, nullptr, 0.125f, 1);
    gemm_kernel<<<gemm_grid, 256>>>(x, Wk, bk, pk, SEQ, DM, DM, nullptr, 1.0f, 1);
    gemm_kernel<<<gemm_grid, 256>>>(x, Wv, bv, pv, SEQ, DM, DM, nullptr, 1.0f, 1);

    // sliding-window attention (fp32)
    attn_kernel<<<dim3(SEQ / 64, NH), 256>>>(pattno);

    // Wo projection + residual(hidden) -> LN1 -> x1 (fp32)
    gemm_kernel<<<gemm_grid, 256>>>(pattno, Wo, bo, ptmp, SEQ, DM, DM, x, 1.0f, 2);
    ln_kernel<<<SEQ, 256>>>(ptmp, ln1g, ln1b, px1);

    // gating (fp32-exact; writes gate_weights output + expert lists)
    gating_kernel<<<SEQ, 256>>>(px1, gateW, gateb, gate_out);

    // MoE expert FFN (tf32 tensor cores, grouped sparse top-2)
    mma_moe_gemm1<<<dim3(FF / BN, SEQ / BM, NE), 256>>>(px1, W1e, b1e);
    mma_moe_gemm2<<<dim3(DM / BN, SEQ / BM, NE), 256>>>(W2e, b2e);
    combine_kernel<<<SEQ, 192>>>();

    // Wd projection (tf32) + residual(x1) -> LN2 -> layer_output
    mma_gemm_res<<<gemm_grid, 256>>>(pmoe, Wd, bd, ptmp, px1, SEQ, DM, DM);
    ln_kernel<<<SEQ, 256>>>(ptmp, ln2g, ln2b, out);
}

// round 11
// speedup vs baseline: 1.2045x; 1.2045x over previous
#include <cuda_runtime.h>
#include <math.h>

#define SEQ 4096
#define DM  768
#define NH  12
#define DH  64
#define FF  3072
#define NE  7
#define WIN 256
#define CAP 4096

// ---------------- scratch (static device globals; no allocation) ----------------
__device__ float g_q[NH * SEQ * DH];
__device__ float g_k[NH * SEQ * DH];
__device__ float g_v[NH * SEQ * DH];
__device__ float g_attno[SEQ * DM];
__device__ float g_tmp[SEQ * DM];
__device__ float g_x1[SEQ * DM];
__device__ float g_moe[SEQ * DM];
__device__ float g_h[NE * CAP * FF];     // 352 MB
__device__ float g_eo[NE * CAP * DM];    // 88 MB
__device__ int   g_cnt[NE];
__device__ int   g_tok[NE * CAP];
__device__ float g_wl[NE * CAP];
__device__ int   g_pos[SEQ * 2];

// ---------------- reset ----------------
__global__ void reset_kernel() {
    if (threadIdx.x < NE) g_cnt[threadIdx.x] = 0;
}

// ======================================================================
// fp32 SIMT GEMM, double-buffered (gating-critical path: QKV, Wo)
// BM=128, BN=64, BK=16, 256 threads, 8x4 per thread
// ======================================================================
#define BM 128
#define BN 64
#define BK 16

// fp32 compute micro-tile on one smem stage
__device__ __forceinline__ void f32_compute(
    const float (*As)[BM], const float (*Bs)[BN],
    float acc[8][4], int rg, int cg)
{
#pragma unroll
    for (int k = 0; k < BK; k++) {
        float4 a0 = *(const float4*)&As[k][rg * 8];
        float4 a1 = *(const float4*)&As[k][rg * 8 + 4];
        float4 b0 = *(const float4*)&Bs[k][cg * 4];
        float a[8] = {a0.x, a0.y, a0.z, a0.w, a1.x, a1.y, a1.z, a1.w};
        float b[4] = {b0.x, b0.y, b0.z, b0.w};
#pragma unroll
        for (int i = 0; i < 8; i++)
#pragma unroll
            for (int j = 0; j < 4; j++) acc[i][j] += a[i] * b[j];
    }
}

// generic fp32 GEMM with epilogue modes (0: bias, 1: qkv-scatter, 2: bias+res)
__global__ __launch_bounds__(256) void gemm_kernel(
    const float* __restrict__ A, const float* __restrict__ B,
    const float* __restrict__ bias, float* __restrict__ C,
    int M, int N, int K, const float* __restrict__ residual,
    float scale, int mode)
{
    __shared__ __align__(16) float As[2][BK][BM];
    __shared__ __align__(16) float Bs[2][BK][BN];
    int tid = threadIdx.x;
    int m0 = blockIdx.y * BM;
    int n0 = blockIdx.x * BN;
    int rg = tid >> 4, cg = tid & 15;
    int ar = tid >> 2, ac = (tid & 3) << 2;
    int br = tid >> 4, bc = (tid & 15) << 2;

    float acc[8][4];
#pragma unroll
    for (int i = 0; i < 8; i++)
#pragma unroll
        for (int j = 0; j < 4; j++) acc[i][j] = 0.f;

    float4 av0, av1, bv;
    // prologue: load k-block 0
    av0 = *(const float4*)&A[(size_t)(m0 + ar) * K + ac];
    av1 = *(const float4*)&A[(size_t)(m0 + ar + 64) * K + ac];
    bv  = *(const float4*)&B[(size_t)br * N + n0 + bc];
    {
        As[0][ac + 0][ar] = av0.x; As[0][ac + 1][ar] = av0.y;
        As[0][ac + 2][ar] = av0.z; As[0][ac + 3][ar] = av0.w;
        As[0][ac + 0][ar + 64] = av1.x; As[0][ac + 1][ar + 64] = av1.y;
        As[0][ac + 2][ar + 64] = av1.z; As[0][ac + 3][ar + 64] = av1.w;
        *(float4*)&Bs[0][br][bc] = bv;
    }
    __syncthreads();

    int nkb = K / BK;
    for (int kb = 0; kb < nkb; kb++) {
        int buf = kb & 1;
        int k0n = (kb + 1) * BK;
        if (kb + 1 < nkb) {
            av0 = *(const float4*)&A[(size_t)(m0 + ar) * K + k0n + ac];
            av1 = *(const float4*)&A[(size_t)(m0 + ar + 64) * K + k0n + ac];
            bv  = *(const float4*)&B[(size_t)(k0n + br) * N + n0 + bc];
        }
        f32_compute(As[buf], Bs[buf], acc, rg, cg);
        if (kb + 1 < nkb) {
            int nb = buf ^ 1;
            As[nb][ac + 0][ar] = av0.x; As[nb][ac + 1][ar] = av0.y;
            As[nb][ac + 2][ar] = av0.z; As[nb][ac + 3][ar] = av0.w;
            As[nb][ac + 0][ar + 64] = av1.x; As[nb][ac + 1][ar + 64] = av1.y;
            As[nb][ac + 2][ar + 64] = av1.z; As[nb][ac + 3][ar + 64] = av1.w;
            *(float4*)&Bs[nb][br][bc] = bv;
        }
        __syncthreads();
    }

#pragma unroll
    for (int i = 0; i < 8; i++) {
        int row = m0 + rg * 8 + i;
#pragma unroll
        for (int j = 0; j < 4; j++) {
            int col = n0 + cg * 4 + j;
            float v = acc[i][j] + bias[col];
            if (mode == 0) {
                C[(size_t)row * N + col] = v;
            } else if (mode == 1) {
                C[((size_t)(col >> 6) * M + row) * 64 + (col & 63)] = v * scale;
            } else {
                C[(size_t)row * N + col] = v + residual[(size_t)row * N + col];
            }
        }
    }
}

// fused QKV: grid.z selects which projection; mode-1 (head-scatter) epilogue
__global__ __launch_bounds__(256) void qkv_gemm_kernel(
    const float* __restrict__ A,
    const float* __restrict__ W0, const float* __restrict__ W1, const float* __restrict__ W2,
    const float* __restrict__ b0, const float* __restrict__ b1, const float* __restrict__ b2,
    float* __restrict__ C0, float* __restrict__ C1, float* __restrict__ C2)
{
    int which = blockIdx.z;
    const float* B    = which == 0 ? W0 : (which == 1 ? W1 : W2);
    const float* bias = which == 0 ? b0 : (which == 1 ? b1 : b2);
    float* C          = which == 0 ? C0 : (which == 1 ? C1 : C2);
    float scale       = which == 0 ? 0.125f : 1.0f;
    const int N = DM, K = DM, M = SEQ;

    __shared__ __align__(16) float As[2][BK][BM];
    __shared__ __align__(16) float Bs[2][BK][BN];
    int tid = threadIdx.x;
    int m0 = blockIdx.y * BM;
    int n0 = blockIdx.x * BN;
    int rg = tid >> 4, cg = tid & 15;
    int ar = tid >> 2, ac = (tid & 3) << 2;
    int br = tid >> 4, bc = (tid & 15) << 2;

    float acc[8][4];
#pragma unroll
    for (int i = 0; i < 8; i++)
#pragma unroll
        for (int j = 0; j < 4; j++) acc[i][j] = 0.f;

    float4 av0, av1, bv;
    av0 = *(const float4*)&A[(size_t)(m0 + ar) * K + ac];
    av1 = *(const float4*)&A[(size_t)(m0 + ar + 64) * K + ac];
    bv  = *(const float4*)&B[(size_t)br * N + n0 + bc];
    {
        As[0][ac + 0][ar] = av0.x; As[0][ac + 1][ar] = av0.y;
        As[0][ac + 2][ar] = av0.z; As[0][ac + 3][ar] = av0.w;
        As[0][ac + 0][ar + 64] = av1.x; As[0][ac + 1][ar + 64] = av1.y;
        As[0][ac + 2][ar + 64] = av1.z; As[0][ac + 3][ar + 64] = av1.w;
        *(float4*)&Bs[0][br][bc] = bv;
    }
    __syncthreads();

    int nkb = K / BK;
    for (int kb = 0; kb < nkb; kb++) {
        int buf = kb & 1;
        int k0n = (kb + 1) * BK;
        if (kb + 1 < nkb) {
            av0 = *(const float4*)&A[(size_t)(m0 + ar) * K + k0n + ac];
            av1 = *(const float4*)&A[(size_t)(m0 + ar + 64) * K + k0n + ac];
            bv  = *(const float4*)&B[(size_t)(k0n + br) * N + n0 + bc];
        }
        f32_compute(As[buf], Bs[buf], acc, rg, cg);
        if (kb + 1 < nkb) {
            int nb = buf ^ 1;
            As[nb][ac + 0][ar] = av0.x; As[nb][ac + 1][ar] = av0.y;
            As[nb][ac + 2][ar] = av0.z; As[nb][ac + 3][ar] = av0.w;
            As[nb][ac + 0][ar + 64] = av1.x; As[nb][ac + 1][ar + 64] = av1.y;
            As[nb][ac + 2][ar + 64] = av1.z; As[nb][ac + 3][ar + 64] = av1.w;
            *(float4*)&Bs[nb][br][bc] = bv;
        }
        __syncthreads();
    }

#pragma unroll
    for (int i = 0; i < 8; i++) {
        int row = m0 + rg * 8 + i;
#pragma unroll
        for (int j = 0; j < 4; j++) {
            int col = n0 + cg * 4 + j;
            float v = (acc[i][j] + bias[col]) * scale;
            C[((size_t)(col >> 6) * M + row) * 64 + (col & 63)] = v;
        }
    }
}

// ======================================================================
// tf32 tensor-core GEMM v2 (mma.sync.m16n8k8)
// BM=128, BN=128, BK=16, 256 threads = 8 warps (2m x 4n), warp tile 64x32.
// Double-buffered smem, LDG prefetch overlapping MMA.
// ======================================================================
#define TBM 128
#define TBN 128
#define TBK 16
#define TSTR 136   // +8 pad: conflict-free fragment loads

__device__ __forceinline__ unsigned f2tf(float f) {
    unsigned u;
    asm("cvt.rna.tf32.f32 %0, %1;" : "=r"(u) : "f"(f));
    return u;
}

__device__ __forceinline__ void mma_tf32(float* c, const unsigned* a, const unsigned* b) {
    asm volatile(
        "mma.sync.aligned.m16n8k8.row.col.f32.tf32.tf32.f32 "
        "{%0,%1,%2,%3}, {%4,%5,%6,%7}, {%8,%9}, {%0,%1,%2,%3};"
        : "+f"(c[0]), "+f"(c[1]), "+f"(c[2]), "+f"(c[3])
        : "r"(a[0]), "r"(a[1]), "r"(a[2]), "r"(a[3]),
          "r"(b[0]), "r"(b[1]));
}

__device__ __forceinline__ void tf32_compute(
    const unsigned (*As)[TSTR], const unsigned (*Bs)[TSTR],
    float acc[4][4][4], int m0w, int n0w, int g, int t)
{
#pragma unroll
    for (int kk = 0; kk < TBK; kk += 8) {
        unsigned afr[4][4], bfr[4][2];
#pragma unroll
        for (int mi = 0; mi < 4; mi++) {
            int mb = m0w + mi * 16 + g;
            afr[mi][0] = As[kk + t][mb];
            afr[mi][1] = As[kk + t][mb + 8];
            afr[mi][2] = As[kk + t + 4][mb];
            afr[mi][3] = As[kk + t + 4][mb + 8];
        }
#pragma unroll
        for (int ni = 0; ni < 4; ni++) {
            int nb = n0w + ni * 8 + g;
            bfr[ni][0] = Bs[kk + t][nb];
            bfr[ni][1] = Bs[kk + t + 4][nb];
        }
#pragma unroll
        for (int mi = 0; mi < 4; mi++)
#pragma unroll
            for (int ni = 0; ni < 4; ni++)
                mma_tf32(acc[mi][ni], afr[mi], bfr[ni]);
    }
}

// common decls for tf32 kernels
#define TF32_DECLS()                                                       \
    __shared__ __align__(16) unsigned As[2][TBK][TSTR];                    \
    __shared__ __align__(16) unsigned Bs[2][TBK][TSTR];                    \
    int tid = threadIdx.x;                                                 \
    int arow = tid >> 2, acol = (tid & 3) << 2;                            \
    int brow = tid >> 4, bcol = (tid & 15) << 3;                           \
    int w = tid >> 5, lane = tid & 31;                                     \
    int m0w = (w >> 2) * 64, n0w = (w & 3) * 32;                           \
    int g = lane >> 2, t = lane & 3;                                       \
    float4 av0, av1, bv0, bv1;                                             \
    float acc[4][4][4];                                                    \
    _Pragma("unroll")                                                      \
    for (int mi = 0; mi < 4; mi++)                                         \
        _Pragma("unroll")                                                  \
        for (int ni = 0; ni < 4; ni++)                                     \
            _Pragma("unroll")                                              \
            for (int j = 0; j < 4; j++) acc[mi][ni][j] = 0.f;

#define TF32_STORE(buf)                                                    \
    {                                                                      \
        As[buf][acol + 0][arow] = f2tf(av0.x);                             \
        As[buf][acol + 1][arow] = f2tf(av0.y);                             \
        As[buf][acol + 2][arow] = f2tf(av0.z);                             \
        As[buf][acol + 3][arow] = f2tf(av0.w);                             \
        As[buf][acol + 0][arow + 64] = f2tf(av1.x);                        \
        As[buf][acol + 1][arow + 64] = f2tf(av1.y);                        \
        As[buf][acol + 2][arow + 64] = f2tf(av1.z);                        \
        As[buf][acol + 3][arow + 64] = f2tf(av1.w);                        \
        uint4 u0, u1;                                                      \
        u0.x = f2tf(bv0.x); u0.y = f2tf(bv0.y);                            \
        u0.z = f2tf(bv0.z); u0.w = f2tf(bv0.w);                            \
        u1.x = f2tf(bv1.x); u1.y = f2tf(bv1.y);                            \
        u1.z = f2tf(bv1.z); u1.w = f2tf(bv1.w);                            \
        *(uint4*)&Bs[buf][brow][bcol] = u0;                                \
        *(uint4*)&Bs[buf][brow][bcol + 4] = u1;                            \
    }

// ---------------- MoE GEMM 1 (tf32): gather + GELU ----------------
__global__ __launch_bounds__(256) void mma_moe_gemm1(
    const float* __restrict__ X, const float* __restrict__ W1,
    const float* __restrict__ b1)
{
    int e = blockIdx.z;
    int M = g_cnt[e];
    int m0 = blockIdx.y * TBM;
    if (m0 >= M) return;
    const float* B = W1 + (size_t)e * DM * FF;
    const float* bias = b1 + (size_t)e * FF;
    float* C = g_h + (size_t)e * CAP * FF;
    const int* tl = g_tok + e * CAP;
    int n0 = blockIdx.x * TBN;

    TF32_DECLS();

    int trow0 = (m0 + arow      < M) ? tl[m0 + arow]      : -1;
    int trow1 = (m0 + arow + 64 < M) ? tl[m0 + arow + 64] : -1;

#define G1_LOADA(K0)                                                          \
    av0 = (trow0 >= 0) ? *(const float4*)&X[(size_t)trow0 * DM + (K0) + acol] \
                       : make_float4(0.f, 0.f, 0.f, 0.f);                     \
    av1 = (trow1 >= 0) ? *(const float4*)&X[(size_t)trow1 * DM + (K0) + acol] \
                       : make_float4(0.f, 0.f, 0.f, 0.f);
#define G1_LOADB(K0)                                                          \
    bv0 = *(const float4*)&B[(size_t)((K0) + brow) * FF + n0 + bcol];         \
    bv1 = *(const float4*)&B[(size_t)((K0) + brow) * FF + n0 + bcol + 4];

    G1_LOADA(0); G1_LOADB(0); TF32_STORE(0);
    __syncthreads();

    const int nkb = DM / TBK;
    for (int kb = 0; kb < nkb; kb++) {
        int buf = kb & 1;
        int k0n = (kb + 1) * TBK;
        if (kb + 1 < nkb) { G1_LOADA(k0n); G1_LOADB(k0n); }
        tf32_compute(As[buf], Bs[buf], acc, m0w, n0w, g, t);
        if (kb + 1 < nkb) { int nb = buf ^ 1; TF32_STORE(nb); }
        __syncthreads();
    }

#pragma unroll
    for (int mi = 0; mi < 4; mi++) {
#pragma unroll
        for (int ni = 0; ni < 4; ni++) {
            int col = n0 + n0w + ni * 8 + 2 * t;
            float bvv0 = bias[col], bvv1 = bias[col + 1];
#pragma unroll
            for (int half = 0; half < 2; half++) {
                int row = m0 + m0w + mi * 16 + g + half * 8;
                if (row >= M) continue;
                float v0 = acc[mi][ni][half * 2 + 0] + bvv0;
                float v1 = acc[mi][ni][half * 2 + 1] + bvv1;
                v0 = 0.5f * v0 * (1.f + erff(v0 * 0.70710678118654752f));
                v1 = 0.5f * v1 * (1.f + erff(v1 * 0.70710678118654752f));
                C[(size_t)row * FF + col]     = v0;
                C[(size_t)row * FF + col + 1] = v1;
            }
        }
    }
}

// ---------------- MoE GEMM 2 (tf32): * gate weight ----------------
__global__ __launch_bounds__(256) void mma_moe_gemm2(
    const float* __restrict__ W2, const float* __restrict__ b2)
{
    int e = blockIdx.z;
    int M = g_cnt[e];
    int m0 = blockIdx.y * TBM;
    if (m0 >= M) return;
    const float* A = g_h + (size_t)e * CAP * FF;
    const float* B = W2 + (size_t)e * FF * DM;
    const float* bias = b2 + (size_t)e * DM;
    const float* wl = g_wl + e * CAP;
    float* C = g_eo + (size_t)e * CAP * DM;
    int n0 = blockIdx.x * TBN;

    TF32_DECLS();

    bool r0ok = (m0 + arow < M), r1ok = (m0 + arow + 64 < M);

#define G2_LOADA(K0)                                                            \
    av0 = r0ok ? *(const float4*)&A[(size_t)(m0 + arow) * FF + (K0) + acol]     \
               : make_float4(0.f, 0.f, 0.f, 0.f);                               \
    av1 = r1ok ? *(const float4*)&A[(size_t)(m0 + arow + 64) * FF + (K0) + acol]\
               : make_float4(0.f, 0.f, 0.f, 0.f);
#define G2_LOADB(K0)                                                            \
    bv0 = *(const float4*)&B[(size_t)((K0) + brow) * DM + n0 + bcol];           \
    bv1 = *(const float4*)&B[(size_t)((K0) + brow) * DM + n0 + bcol + 4];

    G2_LOADA(0); G2_LOADB(0); TF32_STORE(0);
    __syncthreads();

    const int nkb = FF / TBK;
    for (int kb = 0; kb < nkb; kb++) {
        int buf = kb & 1;
        int k0n = (kb + 1) * TBK;
        if (kb + 1 < nkb) { G2_LOADA(k0n); G2_LOADB(k0n); }
        tf32_compute(As[buf], Bs[buf], acc, m0w, n0w, g, t);
        if (kb + 1 < nkb) { int nb = buf ^ 1; TF32_STORE(nb); }
        __syncthreads();
    }

#pragma unroll
    for (int mi = 0; mi < 4; mi++) {
#pragma unroll
        for (int ni = 0; ni < 4; ni++) {
            int col = n0 + n0w + ni * 8 + 2 * t;
            float bvv0 = bias[col], bvv1 = bias[col + 1];
#pragma unroll
            for (int half = 0; half < 2; half++) {
                int row = m0 + m0w + mi * 16 + g + half * 8;
                if (row >= M) continue;
                float wv = wl[row];
                C[(size_t)row * DM + col]     = (acc[mi][ni][half * 2 + 0] + bvv0) * wv;
                C[(size_t)row * DM + col + 1] = (acc[mi][ni][half * 2 + 1] + bvv1) * wv;
            }
        }
    }
}

// ---------------- Wd GEMM (tf32): + bias + residual ----------------
__global__ __launch_bounds__(256) void mma_gemm_res(
    const float* __restrict__ A, const float* __restrict__ B,
    const float* __restrict__ bias, float* __restrict__ C,
    const float* __restrict__ R, int M, int N, int K)
{
    int m0 = blockIdx.y * TBM;
    int n0 = blockIdx.x * TBN;

    TF32_DECLS();

#define GR_LOADA(K0)                                                            \
    av0 = *(const float4*)&A[(size_t)(m0 + arow) * K + (K0) + acol];            \
    av1 = *(const float4*)&A[(size_t)(m0 + arow + 64) * K + (K0) + acol];
#define GR_LOADB(K0)                                                            \
    bv0 = *(const float4*)&B[(size_t)((K0) + brow) * N + n0 + bcol];            \
    bv1 = *(const float4*)&B[(size_t)((K0) + brow) * N + n0 + bcol + 4];

    GR_LOADA(0); GR_LOADB(0); TF32_STORE(0);
    __syncthreads();

    const int nkb = DM / TBK;
    for (int kb = 0; kb < nkb; kb++) {
        int buf = kb & 1;
        int k0n = (kb + 1) * TBK;
        if (kb + 1 < nkb) { GR_LOADA(k0n); GR_LOADB(k0n); }
        tf32_compute(As[buf], Bs[buf], acc, m0w, n0w, g, t);
        if (kb + 1 < nkb) { int nb = buf ^ 1; TF32_STORE(nb); }
        __syncthreads();
    }

#pragma unroll
    for (int mi = 0; mi < 4; mi++) {
#pragma unroll
        for (int ni = 0; ni < 4; ni++) {
            int col = n0 + n0w + ni * 8 + 2 * t;
            float bvv0 = bias[col], bvv1 = bias[col + 1];
#pragma unroll
            for (int half = 0; half < 2; half++) {
                int row = m0 + m0w + mi * 16 + g + half * 8;
                size_t idx = (size_t)row * N + col;
                C[idx]     = acc[mi][ni][half * 2 + 0] + bvv0 + R[idx];
                C[idx + 1] = acc[mi][ni][half * 2 + 1] + bvv1 + R[idx + 1];
            }
        }
    }
}

// ---------------- fused sliding-window attention ----------------
#define APAD 68
__global__ __launch_bounds__(256) void attn_kernel(float* __restrict__ out)
{
    __shared__ float Qs[64][APAD];
    __shared__ float Ks[32][APAD];
    __shared__ float Vs[32][APAD];
    __shared__ float Ss[64][33];
    __shared__ float mS[64], lS[64], cS[64];

    int h = blockIdx.y;
    int q0 = blockIdx.x * 64;
    int tid = threadIdx.x;
    int q = tid & 63;
    int kg = tid >> 6;
    int dp = tid >> 6;

    const float* qhead = g_q + (size_t)h * SEQ * DH;
    const float* khead = g_k + (size_t)h * SEQ * DH;
    const float* vhead = g_v + (size_t)h * SEQ * DH;

#pragma unroll
    for (int i = 0; i < 4; i++) {
        int idx = tid + i * 256;
        int r = idx >> 4;
        int c = (idx & 15) << 2;
        float4 v = *(const float4*)&qhead[(size_t)(q0 + r) * DH + c];
        *(float4*)&Qs[r][c] = v;
    }
    if (tid < 64) { mS[tid] = -1e9f; lS[tid] = 0.f; }

    float acc[16];
#pragma unroll
    for (int i = 0; i < 16; i++) acc[i] = 0.f;
    __syncthreads();

    for (int kt = 0; kt < 18; kt++) {
        int kbase = q0 - 256 + kt * 32;
        if (kbase + 31 < 0 || kbase >= SEQ) continue;

#pragma unroll
        for (int i = 0; i < 2; i++) {
            int idx = tid + i * 256;
            int r = idx >> 4;
            int c = (idx & 15) << 2;
            int kpos = kbase + r;
            float4 kv = make_float4(0.f, 0.f, 0.f, 0.f);
            float4 vv = kv;
            if (kpos >= 0 && kpos < SEQ) {
                kv = *(const float4*)&khead[(size_t)kpos * DH + c];
                vv = *(const float4*)&vhead[(size_t)kpos * DH + c];
            }
            *(float4*)&Ks[r][c] = kv;
            *(float4*)&Vs[r][c] = vv;
        }
        __syncthreads();

        float s[8];
#pragma unroll
        for (int j = 0; j < 8; j++) s[j] = 0.f;
#pragma unroll
        for (int d = 0; d < 64; d += 4) {
            float4 q4 = *(const float4*)&Qs[q][d];
#pragma unroll
            for (int j = 0; j < 8; j++) {
                float4 k4 = *(const float4*)&Ks[kg * 8 + j][d];
                s[j] += q4.x * k4.x + q4.y * k4.y + q4.z * k4.z + q4.w * k4.w;
            }
        }
        int qpos = q0 + q;
#pragma unroll
        for (int j = 0; j < 8; j++) {
            int kpos = kbase + kg * 8 + j;
            bool valid = (kpos >= 0) && (kpos < SEQ) &&
                         (kpos >= qpos - WIN) && (kpos <= qpos + WIN);
            Ss[q][kg * 8 + j] = valid ? s[j] : -1e9f;
        }
        __syncthreads();

        if (tid < 64) {
            int r = tid;
            float mold = mS[r];
            float tmax = -1e9f;
#pragma unroll
            for (int kk = 0; kk < 32; kk++) tmax = fmaxf(tmax, Ss[r][kk]);
            float mnew = fmaxf(mold, tmax);
            float corr = __expf(mold - mnew);
            float sum = 0.f;
#pragma unroll
            for (int kk = 0; kk < 32; kk++) {
                float p = __expf(Ss[r][kk] - mnew);
                Ss[r][kk] = p;
                sum += p;
            }
            lS[r] = lS[r] * corr + sum;
            mS[r] = mnew;
            cS[r] = corr;
        }
        __syncthreads();

        float corr = cS[q];
#pragma unroll
        for (int i = 0; i < 16; i++) acc[i] *= corr;
#pragma unroll
        for (int kk = 0; kk < 32; kk++) {
            float p = Ss[q][kk];
#pragma unroll
            for (int i4 = 0; i4 < 4; i4++) {
                float4 v4 = *(const float4*)&Vs[kk][dp * 16 + i4 * 4];
                acc[i4 * 4 + 0] += p * v4.x;
                acc[i4 * 4 + 1] += p * v4.y;
                acc[i4 * 4 + 2] += p * v4.z;
                acc[i4 * 4 + 3] += p * v4.w;
            }
        }
        __syncthreads();
    }

    float inv = 1.f / lS[q];
    float* o = out + (size_t)(q0 + q) * DM + h * DH + dp * 16;
#pragma unroll
    for (int i4 = 0; i4 < 4; i4++) {
        float4 v;
        v.x = acc[i4 * 4 + 0] * inv;
        v.y = acc[i4 * 4 + 1] * inv;
        v.z = acc[i4 * 4 + 2] * inv;
        v.w = acc[i4 * 4 + 3] * inv;
        *(float4*)&o[i4 * 4] = v;
    }
}

// ---------------- layer norm (row-wise) ----------------
__global__ __launch_bounds__(256) void ln_kernel(
    const float* __restrict__ in, const float* __restrict__ g,
    const float* __restrict__ b, float* __restrict__ out)
{
    __shared__ float rs[8], rs2[8];
    int row = blockIdx.x;
    int tid = threadIdx.x;
    const float* x = in + (size_t)row * DM;
    float vals[3];
    float s = 0.f, s2 = 0.f;
#pragma unroll
    for (int i = 0; i < 3; i++) {
        float v = x[tid + i * 256];
        vals[i] = v;
        s += v;
        s2 += v * v;
    }
    int lane = tid & 31, w = tid >> 5;
#pragma unroll
    for (int o = 16; o; o >>= 1) {
        s += __shfl_down_sync(0xffffffffu, s, o);
        s2 += __shfl_down_sync(0xffffffffu, s2, o);
    }
    if (lane == 0) { rs[w] = s; rs2[w] = s2; }
    __syncthreads();
    if (tid == 0) {
        float a = 0.f, c = 0.f;
#pragma unroll
        for (int i = 0; i < 8; i++) { a += rs[i]; c += rs2[i]; }
        rs[0] = a;
        rs2[0] = c;
    }
    __syncthreads();
    float mean = rs[0] * (1.f / DM);
    float var = rs2[0] * (1.f / DM) - mean * mean;
    float rstd = rsqrtf(var + 1e-5f);
    float* o = out + (size_t)row * DM;
#pragma unroll
    for (int i = 0; i < 3; i++) {
        int col = tid + i * 256;
        o[col] = (vals[i] - mean) * rstd * g[col] + b[col];
    }
}

// ---------------- gating: logits, top-2, softmax, expert lists ----------------
__global__ __launch_bounds__(256) void gating_kernel(
    const float* __restrict__ x1, const float* __restrict__ gW,
    const float* __restrict__ gb, float* __restrict__ gate_out)
{
    __shared__ float xs[DM];
    __shared__ float lg[8];
    int row = blockIdx.x;
    int tid = threadIdx.x;
    for (int i = tid; i < DM; i += 256) xs[i] = x1[(size_t)row * DM + i];
    __syncthreads();
    int w = tid >> 5, lane = tid & 31;
    if (w < NE) {
        float p = 0.f;
        for (int d = lane; d < DM; d += 32) p += xs[d] * gW[d * NE + w];
#pragma unroll
        for (int o = 16; o; o >>= 1) p += __shfl_down_sync(0xffffffffu, p, o);
        if (lane == 0) lg[w] = p + gb[w];
    }
    __syncthreads();
    if (tid == 0) {
        int e1 = 0;
        float v1 = lg[0];
        for (int e = 1; e < NE; e++)
            if (lg[e] > v1) { v1 = lg[e]; e1 = e; }
        int e2 = -1;
        float v2 = -1e30f;
        for (int e = 0; e < NE; e++) {
            if (e == e1) continue;
            if (lg[e] > v2) { v2 = lg[e]; e2 = e; }
        }
        float z = expf(v2 - v1);
        float w1 = 1.f / (1.f + z);
        float w2 = z / (1.f + z);
        float* go = gate_out + (size_t)row * NE;
#pragma unroll
        for (int e = 0; e < NE; e++) go[e] = 0.f;
        go[e1] = w1;
        go[e2] = w2;
        int s1 = atomicAdd(&g_cnt[e1], 1);
        g_tok[e1 * CAP + s1] = row;
        g_wl[e1 * CAP + s1] = w1;
        g_pos[row * 2 + 0] = e1 * CAP + s1;
        int s2 = atomicAdd(&g_cnt[e2], 1);
        g_tok[e2 * CAP + s2] = row;
        g_wl[e2 * CAP + s2] = w2;
        g_pos[row * 2 + 1] = e2 * CAP + s2;
    }
}

// ---------------- combine two expert outputs per token ----------------
__global__ __launch_bounds__(192) void combine_kernel()
{
    int t = blockIdx.x;
    int p0 = g_pos[t * 2 + 0];
    int p1 = g_pos[t * 2 + 1];
    const float* a = g_eo + (size_t)p0 * DM;
    const float* b = g_eo + (size_t)p1 * DM;
    float* o = g_moe + (size_t)t * DM;
    int i = threadIdx.x * 4;
    float4 av = *(const float4*)&a[i];
    float4 bv = *(const float4*)&b[i];
    float4 v;
    v.x = av.x + bv.x;
    v.y = av.y + bv.y;
    v.z = av.z + bv.z;
    v.w = av.w + bv.w;
    *(float4*)&o[i] = v;
}

// ---------------- launch ----------------
extern "C" void kernel_launch(void* const* d_in, const int* in_sizes, int n_in,
                              void* d_out, int out_size)
{
    (void)in_sizes; (void)n_in; (void)out_size;
    const float* x     = (const float*)d_in[0];
    const float* Wq    = (const float*)d_in[1];
    const float* bq    = (const float*)d_in[2];
    const float* Wk    = (const float*)d_in[3];
    const float* bk    = (const float*)d_in[4];
    const float* Wv    = (const float*)d_in[5];
    const float* bv    = (const float*)d_in[6];
    const float* Wo    = (const float*)d_in[7];
    const float* bo    = (const float*)d_in[8];
    const float* ln1g  = (const float*)d_in[9];
    const float* ln1b  = (const float*)d_in[10];
    const float* gateW = (const float*)d_in[11];
    const float* gateb = (const float*)d_in[12];
    const float* W1e   = (const float*)d_in[13];
    const float* b1e   = (const float*)d_in[14];
    const float* W2e   = (const float*)d_in[15];
    const float* b2e   = (const float*)d_in[16];
    const float* Wd    = (const float*)d_in[17];
    const float* bd    = (const float*)d_in[18];
    const float* ln2g  = (const float*)d_in[19];
    const float* ln2b  = (const float*)d_in[20];

    float* out = (float*)d_out;
    float* gate_out = out + (size_t)SEQ * DM;

    float *pq, *pk, *pv, *pattno, *ptmp, *px1, *pmoe;
    cudaGetSymbolAddress((void**)&pq, g_q);
    cudaGetSymbolAddress((void**)&pk, g_k);
    cudaGetSymbolAddress((void**)&pv, g_v);
    cudaGetSymbolAddress((void**)&pattno, g_attno);
    cudaGetSymbolAddress((void**)&ptmp, g_tmp);
    cudaGetSymbolAddress((void**)&px1, g_x1);
    cudaGetSymbolAddress((void**)&pmoe, g_moe);

    reset_kernel<<<1, 32>>>();

    // QKV projections fused (fp32 — gating-critical path; q pre-scaled)
    qkv_gemm_kernel<<<dim3(DM / BN, SEQ / BM, 3), 256>>>(
        x, Wq, Wk, Wv, bq, bk, bv, pq, pk, pv);

    // sliding-window attention (fp32)
    attn_kernel<<<dim3(SEQ / 64, NH), 256>>>(pattno);

    // Wo projection + residual(hidden) -> LN1 -> x1 (fp32)
    gemm_kernel<<<dim3(DM / BN, SEQ / BM), 256>>>(pattno, Wo, bo, ptmp, SEQ, DM, DM, x, 1.0f, 2);
    ln_kernel<<<SEQ, 256>>>(ptmp, ln1g, ln1b, px1);

    // gating (fp32-exact; writes gate_weights output + expert lists)
    gating_kernel<<<SEQ, 256>>>(px1, gateW, gateb, gate_out);

    // MoE expert FFN (tf32 tensor cores, grouped sparse top-2)
    mma_moe_gemm1<<<dim3(FF / TBN, CAP / TBM, NE), 256>>>(px1, W1e, b1e);
    mma_moe_gemm2<<<dim3(DM / TBN, CAP / TBM, NE), 256>>>(W2e, b2e);
    combine_kernel<<<SEQ, 192>>>();

    // Wd projection (tf32) + residual(x1) -> LN2 -> layer_output
    mma_gemm_res<<<dim3(DM / TBN, SEQ / TBM), 256>>>(pmoe, Wd, bd, ptmp, px1, SEQ, DM, DM);
    ln_kernel<<<SEQ, 256>>>(ptmp, ln2g, ln2b, out);
}

// round 12
// speedup vs baseline: 1.3473x; 1.1186x over previous
#include <cuda_runtime.h>
#include <math.h>
#include <stdint.h>

#define SEQ 4096
#define DM  768
#define NH  12
#define DH  64
#define FF  3072
#define NE  7
#define WIN 256
#define CAP 4096

// ---------------- scratch (static device globals; no allocation) ----------------
__device__ float g_q[NH * SEQ * DH];
__device__ float g_k[NH * SEQ * DH];
__device__ float g_v[NH * SEQ * DH];
__device__ float g_attno[SEQ * DM];
__device__ float g_tmp[SEQ * DM];
__device__ float g_x1[SEQ * DM];
__device__ float g_moe[SEQ * DM];
__device__ float g_h[NE * CAP * FF];     // 352 MB
__device__ float g_eo[NE * CAP * DM];    // 88 MB
__device__ int   g_cnt[NE];
__device__ int   g_tok[NE * CAP];
__device__ float g_wl[NE * CAP];
__device__ int   g_pos[SEQ * 2];

// ---------------- reset ----------------
__global__ void reset_kernel() {
    if (threadIdx.x < NE) g_cnt[threadIdx.x] = 0;
}

// ======================================================================
// tf32 tensor-core GEMM, cp.async 3-stage pipeline
// BM=128, BN=128, KSTEP=8, 256 threads = 8 warps (2m x 4n), warp 64x32.
// smem holds raw fp32; tf32 conversion at fragment load.
// ======================================================================
#define TBM 128
#define TBN 128
#define KSTEP 8
#define ASTR 12    // 8 + 4 pad (48B rows, 16B-aligned chunks, conflict-free frags)
#define BSTR 132   // 128 + 4 pad

__device__ __forceinline__ unsigned f2tf(float f) {
    unsigned u;
    asm("cvt.rna.tf32.f32 %0, %1;" : "=r"(u) : "f"(f));
    return u;
}
__device__ __forceinline__ float f2tff(float f) {
    float h;
    asm("cvt.rna.tf32.f32 %0, %1;" : "=f"(h) : "f"(f));
    return h;
}

__device__ __forceinline__ void mma_tf32(float* c, const unsigned* a, const unsigned* b) {
    asm volatile(
        "mma.sync.aligned.m16n8k8.row.col.f32.tf32.tf32.f32 "
        "{%0,%1,%2,%3}, {%4,%5,%6,%7}, {%8,%9}, {%0,%1,%2,%3};"
        : "+f"(c[0]), "+f"(c[1]), "+f"(c[2]), "+f"(c[3])
        : "r"(a[0]), "r"(a[1]), "r"(a[2]), "r"(a[3]),
          "r"(b[0]), "r"(b[1]));
}

__device__ __forceinline__ void cp16(uint32_t dst, const void* src, int sz) {
    asm volatile("cp.async.cg.shared.global [%0], [%1], 16, %2;"
                 :: "r"(dst), "l"(src), "r"(sz) : "memory");
}
__device__ __forceinline__ void cp_commit() {
    asm volatile("cp.async.commit_group;" ::: "memory");
}
__device__ __forceinline__ void cp_wait1() {
    asm volatile("cp.async.wait_group 1;" ::: "memory");
}
__device__ __forceinline__ uint32_t smem_u32(const void* p) {
    return (uint32_t)__cvta_generic_to_shared(p);
}

// single-MMA tf32 (RN conversion at fragment load)
__device__ __forceinline__ void frag_rn(
    const float (*As)[ASTR], const float (*Bs)[BSTR],
    float acc[4][4][4], int m0w, int n0w, int g, int t)
{
    unsigned a_[4][4], b_[4][2];
#pragma unroll
    for (int mi = 0; mi < 4; mi++) {
        int mb = m0w + mi * 16 + g;
        a_[mi][0] = f2tf(As[mb][t]);
        a_[mi][1] = f2tf(As[mb + 8][t]);
        a_[mi][2] = f2tf(As[mb][t + 4]);
        a_[mi][3] = f2tf(As[mb + 8][t + 4]);
    }
#pragma unroll
    for (int ni = 0; ni < 4; ni++) {
        int nb = n0w + ni * 8 + g;
        b_[ni][0] = f2tf(Bs[t][nb]);
        b_[ni][1] = f2tf(Bs[t + 4][nb]);
    }
#pragma unroll
    for (int mi = 0; mi < 4; mi++)
#pragma unroll
        for (int ni = 0; ni < 4; ni++)
            mma_tf32(acc[mi][ni], a_[mi], b_[ni]);
}

// tf32x3 error-compensated (~fp32 accuracy): hi*hi + lo*hi + hi*lo
__device__ __forceinline__ void frag_x3(
    const float (*As)[ASTR], const float (*Bs)[BSTR],
    float acc[4][4][4], int m0w, int n0w, int g, int t)
{
    unsigned ahi[4][4], alo[4][4], bhi[4][2], blo[4][2];
#pragma unroll
    for (int mi = 0; mi < 4; mi++) {
        int mb = m0w + mi * 16 + g;
        float av[4] = {As[mb][t], As[mb + 8][t], As[mb][t + 4], As[mb + 8][t + 4]};
#pragma unroll
        for (int j = 0; j < 4; j++) {
            float h = f2tff(av[j]);
            ahi[mi][j] = __float_as_uint(h);
            alo[mi][j] = __float_as_uint(av[j] - h);
        }
    }
#pragma unroll
    for (int ni = 0; ni < 4; ni++) {
        int nb = n0w + ni * 8 + g;
        float bv[2] = {Bs[t][nb], Bs[t + 4][nb]};
#pragma unroll
        for (int j = 0; j < 2; j++) {
            float h = f2tff(bv[j]);
            bhi[ni][j] = __float_as_uint(h);
            blo[ni][j] = __float_as_uint(bv[j] - h);
        }
    }
#pragma unroll
    for (int mi = 0; mi < 4; mi++)
#pragma unroll
        for (int ni = 0; ni < 4; ni++) {
            mma_tf32(acc[mi][ni], alo[mi], bhi[ni]);
            mma_tf32(acc[mi][ni], ahi[mi], blo[ni]);
            mma_tf32(acc[mi][ni], ahi[mi], bhi[ni]);
        }
}

#define PIPE_DECLS()                                                       \
    __shared__ __align__(16) float As[3][TBM][ASTR];                       \
    __shared__ __align__(16) float Bs[3][KSTEP][BSTR];                     \
    int tid = threadIdx.x;                                                 \
    int car = tid >> 1, cac = (tid & 1) * 4;                               \
    int cbr = tid >> 5, cbc = (tid & 31) * 4;                              \
    int w = tid >> 5, lane = tid & 31;                                     \
    int m0w = (w >> 2) * 64, n0w = (w & 3) * 32;                           \
    int g = lane >> 2, t = lane & 3;                                       \
    float acc[4][4][4];                                                    \
    _Pragma("unroll")                                                      \
    for (int mi = 0; mi < 4; mi++)                                         \
        _Pragma("unroll")                                                  \
        for (int ni = 0; ni < 4; ni++)                                     \
            _Pragma("unroll")                                              \
            for (int j = 0; j < 4; j++) acc[mi][ni][j] = 0.f;

// issue one stage: A row chunk + B row chunk, then commit
#define PIPE_ISSUE(s, k0, pz, pa)                                          \
    cp16(smem_u32(&As[s][car][cac]), asrc + (k0), ((pz) & (pa)));          \
    cp16(smem_u32(&Bs[s][cbr][cbc]), bsrc + (size_t)((k0) + cbr) * ldb, (pz)); \
    cp_commit();

#define PIPE_LOOP(FRAG, pa)                                                \
    PIPE_ISSUE(0, 0, 16, pa);                                              \
    PIPE_ISSUE(1, KSTEP, 16, pa);                                          \
    for (int kb = 0; kb < nkb; kb++) {                                     \
        cp_wait1();                                                        \
        __syncthreads();                                                   \
        int k2 = (kb + 2) * KSTEP;                                         \
        int s2 = (kb + 2) % 3;                                             \
        int pz = (kb + 2 < nkb) ? 16 : 0;                                  \
        PIPE_ISSUE(s2, k2, pz, pa);                                        \
        FRAG(As[kb % 3], Bs[kb % 3], acc, m0w, n0w, g, t);                 \
    }

// ---------------- QKV (tf32x3, fp32-accurate): head-scatter epilogue ----------------
__global__ __launch_bounds__(256) void qkv_x3_kernel(
    const float* __restrict__ A,
    const float* __restrict__ W0, const float* __restrict__ W1, const float* __restrict__ W2,
    const float* __restrict__ b0, const float* __restrict__ b1, const float* __restrict__ b2,
    float* __restrict__ C0, float* __restrict__ C1, float* __restrict__ C2)
{
    int which = blockIdx.z;
    const float* B    = which == 0 ? W0 : (which == 1 ? W1 : W2);
    const float* bias = which == 0 ? b0 : (which == 1 ? b1 : b2);
    float* C          = which == 0 ? C0 : (which == 1 ? C1 : C2);
    float scale       = which == 0 ? 0.125f : 1.0f;
    int m0 = blockIdx.y * TBM;
    int n0 = blockIdx.x * TBN;

    PIPE_DECLS();
    const float* asrc = A + (size_t)(m0 + car) * DM + cac;
    const float* bsrc = B + n0 + cbc;
    const int ldb = DM;
    const int nkb = DM / KSTEP;

    PIPE_LOOP(frag_x3, 16);

#pragma unroll
    for (int mi = 0; mi < 4; mi++) {
#pragma unroll
        for (int ni = 0; ni < 4; ni++) {
            int col = n0 + n0w + ni * 8 + 2 * t;
            float bv0 = bias[col], bv1 = bias[col + 1];
#pragma unroll
            for (int half = 0; half < 2; half++) {
                int row = m0 + m0w + mi * 16 + g + half * 8;
                float v0 = (acc[mi][ni][half * 2 + 0] + bv0) * scale;
                float v1 = (acc[mi][ni][half * 2 + 1] + bv1) * scale;
                C[((size_t)(col >> 6) * SEQ + row) * 64 + (col & 63)]       = v0;
                C[((size_t)((col + 1) >> 6) * SEQ + row) * 64 + ((col + 1) & 63)] = v1;
            }
        }
    }
}

// ---------------- Wo (tf32x3, fp32-accurate): + bias + residual ----------------
__global__ __launch_bounds__(256) void gemm_x3_res_kernel(
    const float* __restrict__ A, const float* __restrict__ B,
    const float* __restrict__ bias, float* __restrict__ C,
    const float* __restrict__ R, int K)
{
    int m0 = blockIdx.y * TBM;
    int n0 = blockIdx.x * TBN;

    PIPE_DECLS();
    const float* asrc = A + (size_t)(m0 + car) * K + cac;
    const float* bsrc = B + n0 + cbc;
    const int ldb = DM;
    const int nkb = K / KSTEP;

    PIPE_LOOP(frag_x3, 16);

#pragma unroll
    for (int mi = 0; mi < 4; mi++) {
#pragma unroll
        for (int ni = 0; ni < 4; ni++) {
            int col = n0 + n0w + ni * 8 + 2 * t;
            float bv0 = bias[col], bv1 = bias[col + 1];
#pragma unroll
            for (int half = 0; half < 2; half++) {
                int row = m0 + m0w + mi * 16 + g + half * 8;
                size_t idx = (size_t)row * DM + col;
                C[idx]     = acc[mi][ni][half * 2 + 0] + bv0 + R[idx];
                C[idx + 1] = acc[mi][ni][half * 2 + 1] + bv1 + R[idx + 1];
            }
        }
    }
}

// ---------------- Wd (tf32): + bias + residual ----------------
__global__ __launch_bounds__(256) void gemm_rn_res_kernel(
    const float* __restrict__ A, const float* __restrict__ B,
    const float* __restrict__ bias, float* __restrict__ C,
    const float* __restrict__ R, int K)
{
    int m0 = blockIdx.y * TBM;
    int n0 = blockIdx.x * TBN;

    PIPE_DECLS();
    const float* asrc = A + (size_t)(m0 + car) * K + cac;
    const float* bsrc = B + n0 + cbc;
    const int ldb = DM;
    const int nkb = K / KSTEP;

    PIPE_LOOP(frag_rn, 16);

#pragma unroll
    for (int mi = 0; mi < 4; mi++) {
#pragma unroll
        for (int ni = 0; ni < 4; ni++) {
            int col = n0 + n0w + ni * 8 + 2 * t;
            float bv0 = bias[col], bv1 = bias[col + 1];
#pragma unroll
            for (int half = 0; half < 2; half++) {
                int row = m0 + m0w + mi * 16 + g + half * 8;
                size_t idx = (size_t)row * DM + col;
                C[idx]     = acc[mi][ni][half * 2 + 0] + bv0 + R[idx];
                C[idx + 1] = acc[mi][ni][half * 2 + 1] + bv1 + R[idx + 1];
            }
        }
    }
}

// ---------------- MoE GEMM 1 (tf32): gather + GELU ----------------
__global__ __launch_bounds__(256) void moe_gemm1_kernel(
    const float* __restrict__ X, const float* __restrict__ W1,
    const float* __restrict__ b1)
{
    int e = blockIdx.z;
    int M = g_cnt[e];
    int m0 = blockIdx.y * TBM;
    if (m0 >= M) return;
    const float* B = W1 + (size_t)e * DM * FF;
    const float* bias = b1 + (size_t)e * FF;
    float* C = g_h + (size_t)e * CAP * FF;
    const int* tl = g_tok + e * CAP;
    int n0 = blockIdx.x * TBN;

    PIPE_DECLS();
    int garow = m0 + car;
    int trow = (garow < M) ? tl[garow] : 0;
    int pa = (garow < M) ? 16 : 0;
    const float* asrc = X + (size_t)trow * DM + cac;
    const float* bsrc = B + n0 + cbc;
    const int ldb = FF;
    const int nkb = DM / KSTEP;

    PIPE_LOOP(frag_rn, pa);

#pragma unroll
    for (int mi = 0; mi < 4; mi++) {
#pragma unroll
        for (int ni = 0; ni < 4; ni++) {
            int col = n0 + n0w + ni * 8 + 2 * t;
            float bv0 = bias[col], bv1 = bias[col + 1];
#pragma unroll
            for (int half = 0; half < 2; half++) {
                int row = m0 + m0w + mi * 16 + g + half * 8;
                if (row >= M) continue;
                float v0 = acc[mi][ni][half * 2 + 0] + bv0;
                float v1 = acc[mi][ni][half * 2 + 1] + bv1;
                v0 = 0.5f * v0 * (1.f + erff(v0 * 0.70710678118654752f));
                v1 = 0.5f * v1 * (1.f + erff(v1 * 0.70710678118654752f));
                C[(size_t)row * FF + col]     = v0;
                C[(size_t)row * FF + col + 1] = v1;
            }
        }
    }
}

// ---------------- MoE GEMM 2 (tf32): * gate weight ----------------
__global__ __launch_bounds__(256) void moe_gemm2_kernel(
    const float* __restrict__ W2, const float* __restrict__ b2)
{
    int e = blockIdx.z;
    int M = g_cnt[e];
    int m0 = blockIdx.y * TBM;
    if (m0 >= M) return;
    const float* Ae = g_h + (size_t)e * CAP * FF;
    const float* B = W2 + (size_t)e * FF * DM;
    const float* bias = b2 + (size_t)e * DM;
    const float* wl = g_wl + e * CAP;
    float* C = g_eo + (size_t)e * CAP * DM;
    int n0 = blockIdx.x * TBN;

    PIPE_DECLS();
    int pa = (m0 + car < M) ? 16 : 0;
    const float* asrc = Ae + (size_t)(m0 + car) * FF + cac;
    const float* bsrc = B + n0 + cbc;
    const int ldb = DM;
    const int nkb = FF / KSTEP;

    PIPE_LOOP(frag_rn, pa);

#pragma unroll
    for (int mi = 0; mi < 4; mi++) {
#pragma unroll
        for (int ni = 0; ni < 4; ni++) {
            int col = n0 + n0w + ni * 8 + 2 * t;
            float bv0 = bias[col], bv1 = bias[col + 1];
#pragma unroll
            for (int half = 0; half < 2; half++) {
                int row = m0 + m0w + mi * 16 + g + half * 8;
                if (row >= M) continue;
                float wv = wl[row];
                C[(size_t)row * DM + col]     = (acc[mi][ni][half * 2 + 0] + bv0) * wv;
                C[(size_t)row * DM + col + 1] = (acc[mi][ni][half * 2 + 1] + bv1) * wv;
            }
        }
    }
}

// ---------------- fused sliding-window attention ----------------
#define APAD 68
__global__ __launch_bounds__(256) void attn_kernel(float* __restrict__ out)
{
    __shared__ float Qs[64][APAD];
    __shared__ float Ks[32][APAD];
    __shared__ float Vs[32][APAD];
    __shared__ float Ss[64][33];
    __shared__ float mS[64], lS[64], cS[64];

    int h = blockIdx.y;
    int q0 = blockIdx.x * 64;
    int tid = threadIdx.x;
    int q = tid & 63;
    int kg = tid >> 6;
    int dp = tid >> 6;

    const float* qhead = g_q + (size_t)h * SEQ * DH;
    const float* khead = g_k + (size_t)h * SEQ * DH;
    const float* vhead = g_v + (size_t)h * SEQ * DH;

#pragma unroll
    for (int i = 0; i < 4; i++) {
        int idx = tid + i * 256;
        int r = idx >> 4;
        int c = (idx & 15) << 2;
        float4 v = *(const float4*)&qhead[(size_t)(q0 + r) * DH + c];
        *(float4*)&Qs[r][c] = v;
    }
    if (tid < 64) { mS[tid] = -1e9f; lS[tid] = 0.f; }

    float acc[16];
#pragma unroll
    for (int i = 0; i < 16; i++) acc[i] = 0.f;
    __syncthreads();

    for (int kt = 0; kt < 18; kt++) {
        int kbase = q0 - 256 + kt * 32;
        if (kbase + 31 < 0 || kbase >= SEQ) continue;

#pragma unroll
        for (int i = 0; i < 2; i++) {
            int idx = tid + i * 256;
            int r = idx >> 4;
            int c = (idx & 15) << 2;
            int kpos = kbase + r;
            float4 kv = make_float4(0.f, 0.f, 0.f, 0.f);
            float4 vv = kv;
            if (kpos >= 0 && kpos < SEQ) {
                kv = *(const float4*)&khead[(size_t)kpos * DH + c];
                vv = *(const float4*)&vhead[(size_t)kpos * DH + c];
            }
            *(float4*)&Ks[r][c] = kv;
            *(float4*)&Vs[r][c] = vv;
        }
        __syncthreads();

        float s[8];
#pragma unroll
        for (int j = 0; j < 8; j++) s[j] = 0.f;
#pragma unroll
        for (int d = 0; d < 64; d += 4) {
            float4 q4 = *(const float4*)&Qs[q][d];
#pragma unroll
            for (int j = 0; j < 8; j++) {
                float4 k4 = *(const float4*)&Ks[kg * 8 + j][d];
                s[j] += q4.x * k4.x + q4.y * k4.y + q4.z * k4.z + q4.w * k4.w;
            }
        }
        int qpos = q0 + q;
#pragma unroll
        for (int j = 0; j < 8; j++) {
            int kpos = kbase + kg * 8 + j;
            bool valid = (kpos >= 0) && (kpos < SEQ) &&
                         (kpos >= qpos - WIN) && (kpos <= qpos + WIN);
            Ss[q][kg * 8 + j] = valid ? s[j] : -1e9f;
        }
        __syncthreads();

        if (tid < 64) {
            int r = tid;
            float mold = mS[r];
            float tmax = -1e9f;
#pragma unroll
            for (int kk = 0; kk < 32; kk++) tmax = fmaxf(tmax, Ss[r][kk]);
            float mnew = fmaxf(mold, tmax);
            float corr = __expf(mold - mnew);
            float sum = 0.f;
#pragma unroll
            for (int kk = 0; kk < 32; kk++) {
                float p = __expf(Ss[r][kk] - mnew);
                Ss[r][kk] = p;
                sum += p;
            }
            lS[r] = lS[r] * corr + sum;
            mS[r] = mnew;
            cS[r] = corr;
        }
        __syncthreads();

        float corr = cS[q];
#pragma unroll
        for (int i = 0; i < 16; i++) acc[i] *= corr;
#pragma unroll
        for (int kk = 0; kk < 32; kk++) {
            float p = Ss[q][kk];
#pragma unroll
            for (int i4 = 0; i4 < 4; i4++) {
                float4 v4 = *(const float4*)&Vs[kk][dp * 16 + i4 * 4];
                acc[i4 * 4 + 0] += p * v4.x;
                acc[i4 * 4 + 1] += p * v4.y;
                acc[i4 * 4 + 2] += p * v4.z;
                acc[i4 * 4 + 3] += p * v4.w;
            }
        }
        __syncthreads();
    }

    float inv = 1.f / lS[q];
    float* o = out + (size_t)(q0 + q) * DM + h * DH + dp * 16;
#pragma unroll
    for (int i4 = 0; i4 < 4; i4++) {
        float4 v;
        v.x = acc[i4 * 4 + 0] * inv;
        v.y = acc[i4 * 4 + 1] * inv;
        v.z = acc[i4 * 4 + 2] * inv;
        v.w = acc[i4 * 4 + 3] * inv;
        *(float4*)&o[i4 * 4] = v;
    }
}

// ---------------- layer norm (row-wise) ----------------
__global__ __launch_bounds__(256) void ln_kernel(
    const float* __restrict__ in, const float* __restrict__ g,
    const float* __restrict__ b, float* __restrict__ out)
{
    __shared__ float rs[8], rs2[8];
    int row = blockIdx.x;
    int tid = threadIdx.x;
    const float* x = in + (size_t)row * DM;
    float vals[3];
    float s = 0.f, s2 = 0.f;
#pragma unroll
    for (int i = 0; i < 3; i++) {
        float v = x[tid + i * 256];
        vals[i] = v;
        s += v;
        s2 += v * v;
    }
    int lane = tid & 31, w = tid >> 5;
#pragma unroll
    for (int o = 16; o; o >>= 1) {
        s += __shfl_down_sync(0xffffffffu, s, o);
        s2 += __shfl_down_sync(0xffffffffu, s2, o);
    }
    if (lane == 0) { rs[w] = s; rs2[w] = s2; }
    __syncthreads();
    if (tid == 0) {
        float a = 0.f, c = 0.f;
#pragma unroll
        for (int i = 0; i < 8; i++) { a += rs[i]; c += rs2[i]; }
        rs[0] = a;
        rs2[0] = c;
    }
    __syncthreads();
    float mean = rs[0] * (1.f / DM);
    float var = rs2[0] * (1.f / DM) - mean * mean;
    float rstd = rsqrtf(var + 1e-5f);
    float* o = out + (size_t)row * DM;
#pragma unroll
    for (int i = 0; i < 3; i++) {
        int col = tid + i * 256;
        o[col] = (vals[i] - mean) * rstd * g[col] + b[col];
    }
}

// ---------------- gating: logits, top-2, softmax, expert lists ----------------
__global__ __launch_bounds__(256) void gating_kernel(
    const float* __restrict__ x1, const float* __restrict__ gW,
    const float* __restrict__ gb, float* __restrict__ gate_out)
{
    __shared__ float xs[DM];
    __shared__ float lg[8];
    int row = blockIdx.x;
    int tid = threadIdx.x;
    for (int i = tid; i < DM; i += 256) xs[i] = x1[(size_t)row * DM + i];
    __syncthreads();
    int w = tid >> 5, lane = tid & 31;
    if (w < NE) {
        float p = 0.f;
        for (int d = lane; d < DM; d += 32) p += xs[d] * gW[d * NE + w];
#pragma unroll
        for (int o = 16; o; o >>= 1) p += __shfl_down_sync(0xffffffffu, p, o);
        if (lane == 0) lg[w] = p + gb[w];
    }
    __syncthreads();
    if (tid == 0) {
        int e1 = 0;
        float v1 = lg[0];
        for (int e = 1; e < NE; e++)
            if (lg[e] > v1) { v1 = lg[e]; e1 = e; }
        int e2 = -1;
        float v2 = -1e30f;
        for (int e = 0; e < NE; e++) {
            if (e == e1) continue;
            if (lg[e] > v2) { v2 = lg[e]; e2 = e; }
        }
        float z = expf(v2 - v1);
        float w1 = 1.f / (1.f + z);
        float w2 = z / (1.f + z);
        float* go = gate_out + (size_t)row * NE;
#pragma unroll
        for (int e = 0; e < NE; e++) go[e] = 0.f;
        go[e1] = w1;
        go[e2] = w2;
        int s1 = atomicAdd(&g_cnt[e1], 1);
        g_tok[e1 * CAP + s1] = row;
        g_wl[e1 * CAP + s1] = w1;
        g_pos[row * 2 + 0] = e1 * CAP + s1;
        int s2 = atomicAdd(&g_cnt[e2], 1);
        g_tok[e2 * CAP + s2] = row;
        g_wl[e2 * CAP + s2] = w2;
        g_pos[row * 2 + 1] = e2 * CAP + s2;
    }
}

// ---------------- combine two expert outputs per token ----------------
__global__ __launch_bounds__(192) void combine_kernel()
{
    int tk = blockIdx.x;
    int p0 = g_pos[tk * 2 + 0];
    int p1 = g_pos[tk * 2 + 1];
    const float* a = g_eo + (size_t)p0 * DM;
    const float* b = g_eo + (size_t)p1 * DM;
    float* o = g_moe + (size_t)tk * DM;
    int i = threadIdx.x * 4;
    float4 av = *(const float4*)&a[i];
    float4 bv = *(const float4*)&b[i];
    float4 v;
    v.x = av.x + bv.x;
    v.y = av.y + bv.y;
    v.z = av.z + bv.z;
    v.w = av.w + bv.w;
    *(float4*)&o[i] = v;
}

// ---------------- launch ----------------
extern "C" void kernel_launch(void* const* d_in, const int* in_sizes, int n_in,
                              void* d_out, int out_size)
{
    (void)in_sizes; (void)n_in; (void)out_size;
    const float* x     = (const float*)d_in[0];
    const float* Wq    = (const float*)d_in[1];
    const float* bq    = (const float*)d_in[2];
    const float* Wk    = (const float*)d_in[3];
    const float* bk    = (const float*)d_in[4];
    const float* Wv    = (const float*)d_in[5];
    const float* bv    = (const float*)d_in[6];
    const float* Wo    = (const float*)d_in[7];
    const float* bo    = (const float*)d_in[8];
    const float* ln1g  = (const float*)d_in[9];
    const float* ln1b  = (const float*)d_in[10];
    const float* gateW = (const float*)d_in[11];
    const float* gateb = (const float*)d_in[12];
    const float* W1e   = (const float*)d_in[13];
    const float* b1e   = (const float*)d_in[14];
    const float* W2e   = (const float*)d_in[15];
    const float* b2e   = (const float*)d_in[16];
    const float* Wd    = (const float*)d_in[17];
    const float* bd    = (const float*)d_in[18];
    const float* ln2g  = (const float*)d_in[19];
    const float* ln2b  = (const float*)d_in[20];

    float* out = (float*)d_out;
    float* gate_out = out + (size_t)SEQ * DM;

    float *pq, *pk, *pv, *pattno, *ptmp, *px1, *pmoe;
    cudaGetSymbolAddress((void**)&pq, g_q);
    cudaGetSymbolAddress((void**)&pk, g_k);
    cudaGetSymbolAddress((void**)&pv, g_v);
    cudaGetSymbolAddress((void**)&pattno, g_attno);
    cudaGetSymbolAddress((void**)&ptmp, g_tmp);
    cudaGetSymbolAddress((void**)&px1, g_x1);
    cudaGetSymbolAddress((void**)&pmoe, g_moe);

    reset_kernel<<<1, 32>>>();

    // QKV projections (tf32x3 ~ fp32 accuracy; q pre-scaled by 1/sqrt(64))
    qkv_x3_kernel<<<dim3(DM / TBN, SEQ / TBM, 3), 256>>>(
        x, Wq, Wk, Wv, bq, bk, bv, pq, pk, pv);

    // sliding-window attention (fp32)
    attn_kernel<<<dim3(SEQ / 64, NH), 256>>>(pattno);

    // Wo projection (tf32x3) + residual(hidden) -> LN1 -> x1
    gemm_x3_res_kernel<<<dim3(DM / TBN, SEQ / TBM), 256>>>(pattno, Wo, bo, ptmp, x, DM);
    ln_kernel<<<SEQ, 256>>>(ptmp, ln1g, ln1b, px1);

    // gating (fp32-exact; writes gate_weights output + expert lists)
    gating_kernel<<<SEQ, 256>>>(px1, gateW, gateb, gate_out);

    // MoE expert FFN (tf32 tensor cores, grouped sparse top-2)
    moe_gemm1_kernel<<<dim3(FF / TBN, CAP / TBM, NE), 256>>>(px1, W1e, b1e);
    moe_gemm2_kernel<<<dim3(DM / TBN, CAP / TBM, NE), 256>>>(W2e, b2e);
    combine_kernel<<<SEQ, 192>>>();

    // Wd projection (tf32) + residual(x1) -> LN2 -> layer_output
    gemm_rn_res_kernel<<<dim3(DM / TBN, SEQ / TBM), 256>>>(pmoe, Wd, bd, ptmp, px1, DM);
    ln_kernel<<<SEQ, 256>>>(ptmp, ln2g, ln2b, out);
}

// round 13
// speedup vs baseline: 1.3816x; 1.0255x over previous
#include <cuda_runtime.h>
#include <math.h>
#include <stdint.h>

#define SEQ 4096
#define DM  768
#define NH  12
#define DH  64
#define FF  3072
#define NE  7
#define WIN 256
#define CAP 4096

// ---------------- scratch (static device globals; no allocation) ----------------
__device__ float g_q[NH * SEQ * DH];
__device__ float g_k[NH * SEQ * DH];
__device__ float g_v[NH * SEQ * DH];
__device__ float g_attno[SEQ * DM];
__device__ float g_tmp[SEQ * DM];
__device__ float g_x1[SEQ * DM];
__device__ float g_moe[SEQ * DM];
__device__ float g_h[NE * CAP * FF];     // 352 MB
__device__ float g_eo[NE * CAP * DM];    // 88 MB
__device__ int   g_cnt[NE];
__device__ int   g_tok[NE * CAP];
__device__ float g_wl[NE * CAP];
__device__ int   g_pos[SEQ * 2];

// ---------------- reset ----------------
__global__ void reset_kernel() {
    if (threadIdx.x < NE) g_cnt[threadIdx.x] = 0;
}

// ======================================================================
// tf32 tensor-core GEMM, cp.async 3-stage pipeline + ldmatrix fragments
// BM=128, BN=128, KSTEP=8, 256 threads = 8 warps (2m x 4n), warp 64x32.
// smem holds raw fp32; tf32 conversion at fragment load (register cvt).
// ======================================================================
#define TBM 128
#define TBN 128
#define KSTEP 8
#define ASTR 12    // 8 + 4 pad: 48B rows, 16B-aligned, ldmatrix conflict-free
#define BSTR 136   // 128 + 8 pad: 8t+g hits all 32 banks -> conflict-free LDS

__device__ __forceinline__ unsigned f2tf(float f) {
    unsigned u;
    asm("cvt.rna.tf32.f32 %0, %1;" : "=r"(u) : "f"(f));
    return u;
}
__device__ __forceinline__ float f2tff(float f) {
    float h;
    asm("cvt.rna.tf32.f32 %0, %1;" : "=f"(h) : "f"(f));
    return h;
}

__device__ __forceinline__ void mma_tf32(float* c, const unsigned* a, const unsigned* b) {
    asm volatile(
        "mma.sync.aligned.m16n8k8.row.col.f32.tf32.tf32.f32 "
        "{%0,%1,%2,%3}, {%4,%5,%6,%7}, {%8,%9}, {%0,%1,%2,%3};"
        : "+f"(c[0]), "+f"(c[1]), "+f"(c[2]), "+f"(c[3])
        : "r"(a[0]), "r"(a[1]), "r"(a[2]), "r"(a[3]),
          "r"(b[0]), "r"(b[1]));
}

__device__ __forceinline__ void ldm_x4(unsigned* r, uint32_t addr) {
    asm volatile("ldmatrix.sync.aligned.m8n8.x4.shared.b16 {%0,%1,%2,%3}, [%4];"
                 : "=r"(r[0]), "=r"(r[1]), "=r"(r[2]), "=r"(r[3]) : "r"(addr));
}

__device__ __forceinline__ void cp16(uint32_t dst, const void* src, int sz) {
    asm volatile("cp.async.cg.shared.global [%0], [%1], 16, %2;"
                 :: "r"(dst), "l"(src), "r"(sz) : "memory");
}
__device__ __forceinline__ void cp_commit() {
    asm volatile("cp.async.commit_group;" ::: "memory");
}
__device__ __forceinline__ void cp_wait1() {
    asm volatile("cp.async.wait_group 1;" ::: "memory");
}
__device__ __forceinline__ uint32_t smem_u32(const void* p) {
    return (uint32_t)__cvta_generic_to_shared(p);
}

// single-MMA tf32 (RN conversion in registers after ldmatrix)
__device__ __forceinline__ void frag_rn(
    const float (*As_)[ASTR], const float (*Bs_)[BSTR],
    float acc[4][4][4], int a_row, int a_col, int n0w, int g, int t)
{
    uint32_t ab = smem_u32(&As_[a_row][a_col]);
    unsigned a_[4][4];
#pragma unroll
    for (int mi = 0; mi < 4; mi++) ldm_x4(a_[mi], ab + mi * 16 * ASTR * 4);
#pragma unroll
    for (int mi = 0; mi < 4; mi++)
#pragma unroll
        for (int j = 0; j < 4; j++)
            a_[mi][j] = f2tf(__uint_as_float(a_[mi][j]));

    unsigned b_[4][2];
#pragma unroll
    for (int ni = 0; ni < 4; ni++) {
        int nb = n0w + ni * 8 + g;
        b_[ni][0] = f2tf(Bs_[t][nb]);
        b_[ni][1] = f2tf(Bs_[t + 4][nb]);
    }
#pragma unroll
    for (int mi = 0; mi < 4; mi++)
#pragma unroll
        for (int ni = 0; ni < 4; ni++)
            mma_tf32(acc[mi][ni], a_[mi], b_[ni]);
}

// tf32x3 error-compensated (~fp32): hi*hi + lo*hi + hi*lo
__device__ __forceinline__ void frag_x3(
    const float (*As_)[ASTR], const float (*Bs_)[BSTR],
    float acc[4][4][4], int a_row, int a_col, int n0w, int g, int t)
{
    uint32_t ab = smem_u32(&As_[a_row][a_col]);
    unsigned araw[4][4];
#pragma unroll
    for (int mi = 0; mi < 4; mi++) ldm_x4(araw[mi], ab + mi * 16 * ASTR * 4);

    unsigned ahi[4][4], alo[4][4], bhi[4][2], blo[4][2];
#pragma unroll
    for (int mi = 0; mi < 4; mi++)
#pragma unroll
        for (int j = 0; j < 4; j++) {
            float f = __uint_as_float(araw[mi][j]);
            float h = f2tff(f);
            ahi[mi][j] = __float_as_uint(h);
            alo[mi][j] = __float_as_uint(f - h);
        }
#pragma unroll
    for (int ni = 0; ni < 4; ni++) {
        int nb = n0w + ni * 8 + g;
        float bv[2] = {Bs_[t][nb], Bs_[t + 4][nb]};
#pragma unroll
        for (int j = 0; j < 2; j++) {
            float h = f2tff(bv[j]);
            bhi[ni][j] = __float_as_uint(h);
            blo[ni][j] = __float_as_uint(bv[j] - h);
        }
    }
#pragma unroll
    for (int mi = 0; mi < 4; mi++)
#pragma unroll
        for (int ni = 0; ni < 4; ni++) {
            mma_tf32(acc[mi][ni], alo[mi], bhi[ni]);
            mma_tf32(acc[mi][ni], ahi[mi], blo[ni]);
            mma_tf32(acc[mi][ni], ahi[mi], bhi[ni]);
        }
}

#define PIPE_DECLS()                                                       \
    __shared__ __align__(16) float As[3][TBM][ASTR];                       \
    __shared__ __align__(16) float Bs[3][KSTEP][BSTR];                     \
    int tid = threadIdx.x;                                                 \
    int car = tid >> 1, cac = (tid & 1) * 4;                               \
    int cbr = tid >> 5, cbc = (tid & 31) * 4;                              \
    int w = tid >> 5, lane = tid & 31;                                     \
    int m0w = (w >> 2) * 64, n0w = (w & 3) * 32;                           \
    int g = lane >> 2, t = lane & 3;                                       \
    int a_row = m0w + (lane & 7) + ((lane >> 3) & 1) * 8;                  \
    int a_col = (lane >> 4) * 4;                                           \
    float acc[4][4][4];                                                    \
    _Pragma("unroll")                                                      \
    for (int mi = 0; mi < 4; mi++)                                         \
        _Pragma("unroll")                                                  \
        for (int ni = 0; ni < 4; ni++)                                     \
            _Pragma("unroll")                                              \
            for (int j = 0; j < 4; j++) acc[mi][ni][j] = 0.f;

// issue one stage: A row chunk + B row chunk, then commit
#define PIPE_ISSUE(s, k0, pz, pa)                                          \
    cp16(smem_u32(&As[s][car][cac]), asrc + (k0), ((pz) & (pa)));          \
    cp16(smem_u32(&Bs[s][cbr][cbc]), bsrc + (size_t)((k0) + cbr) * ldb, (pz)); \
    cp_commit();

#define PIPE_LOOP(FRAG, pa)                                                \
    PIPE_ISSUE(0, 0, 16, pa);                                              \
    PIPE_ISSUE(1, KSTEP, 16, pa);                                          \
    for (int kb = 0; kb < nkb; kb++) {                                     \
        cp_wait1();                                                        \
        __syncthreads();                                                   \
        int k2 = (kb + 2) * KSTEP;                                         \
        int s2 = (kb + 2) % 3;                                             \
        int pz = (kb + 2 < nkb) ? 16 : 0;                                  \
        PIPE_ISSUE(s2, k2, pz, pa);                                        \
        FRAG(As[kb % 3], Bs[kb % 3], acc, a_row, a_col, n0w, g, t);        \
    }

// ---------------- QKV (tf32x3, fp32-accurate): head-scatter epilogue ----------------
__global__ __launch_bounds__(256) void qkv_x3_kernel(
    const float* __restrict__ A,
    const float* __restrict__ W0, const float* __restrict__ W1, const float* __restrict__ W2,
    const float* __restrict__ b0, const float* __restrict__ b1, const float* __restrict__ b2,
    float* __restrict__ C0, float* __restrict__ C1, float* __restrict__ C2)
{
    int which = blockIdx.z;
    const float* B    = which == 0 ? W0 : (which == 1 ? W1 : W2);
    const float* bias = which == 0 ? b0 : (which == 1 ? b1 : b2);
    float* C          = which == 0 ? C0 : (which == 1 ? C1 : C2);
    float scale       = which == 0 ? 0.125f : 1.0f;
    int m0 = blockIdx.y * TBM;
    int n0 = blockIdx.x * TBN;

    PIPE_DECLS();
    const float* asrc = A + (size_t)(m0 + car) * DM + cac;
    const float* bsrc = B + n0 + cbc;
    const int ldb = DM;
    const int nkb = DM / KSTEP;

    PIPE_LOOP(frag_x3, 16);

#pragma unroll
    for (int mi = 0; mi < 4; mi++) {
#pragma unroll
        for (int ni = 0; ni < 4; ni++) {
            int col = n0 + n0w + ni * 8 + 2 * t;
            float bv0 = bias[col], bv1 = bias[col + 1];
#pragma unroll
            for (int half = 0; half < 2; half++) {
                int row = m0 + m0w + mi * 16 + g + half * 8;
                float v0 = (acc[mi][ni][half * 2 + 0] + bv0) * scale;
                float v1 = (acc[mi][ni][half * 2 + 1] + bv1) * scale;
                C[((size_t)(col >> 6) * SEQ + row) * 64 + (col & 63)]       = v0;
                C[((size_t)((col + 1) >> 6) * SEQ + row) * 64 + ((col + 1) & 63)] = v1;
            }
        }
    }
}

// ---------------- Wo (tf32x3, fp32-accurate): + bias + residual ----------------
__global__ __launch_bounds__(256) void gemm_x3_res_kernel(
    const float* __restrict__ A, const float* __restrict__ B,
    const float* __restrict__ bias, float* __restrict__ C,
    const float* __restrict__ R, int K)
{
    int m0 = blockIdx.y * TBM;
    int n0 = blockIdx.x * TBN;

    PIPE_DECLS();
    const float* asrc = A + (size_t)(m0 + car) * K + cac;
    const float* bsrc = B + n0 + cbc;
    const int ldb = DM;
    const int nkb = K / KSTEP;

    PIPE_LOOP(frag_x3, 16);

#pragma unroll
    for (int mi = 0; mi < 4; mi++) {
#pragma unroll
        for (int ni = 0; ni < 4; ni++) {
            int col = n0 + n0w + ni * 8 + 2 * t;
            float bv0 = bias[col], bv1 = bias[col + 1];
#pragma unroll
            for (int half = 0; half < 2; half++) {
                int row = m0 + m0w + mi * 16 + g + half * 8;
                size_t idx = (size_t)row * DM + col;
                C[idx]     = acc[mi][ni][half * 2 + 0] + bv0 + R[idx];
                C[idx + 1] = acc[mi][ni][half * 2 + 1] + bv1 + R[idx + 1];
            }
        }
    }
}

// ---------------- Wd (tf32): + bias + residual ----------------
__global__ __launch_bounds__(256) void gemm_rn_res_kernel(
    const float* __restrict__ A, const float* __restrict__ B,
    const float* __restrict__ bias, float* __restrict__ C,
    const float* __restrict__ R, int K)
{
    int m0 = blockIdx.y * TBM;
    int n0 = blockIdx.x * TBN;

    PIPE_DECLS();
    const float* asrc = A + (size_t)(m0 + car) * K + cac;
    const float* bsrc = B + n0 + cbc;
    const int ldb = DM;
    const int nkb = K / KSTEP;

    PIPE_LOOP(frag_rn, 16);

#pragma unroll
    for (int mi = 0; mi < 4; mi++) {
#pragma unroll
        for (int ni = 0; ni < 4; ni++) {
            int col = n0 + n0w + ni * 8 + 2 * t;
            float bv0 = bias[col], bv1 = bias[col + 1];
#pragma unroll
            for (int half = 0; half < 2; half++) {
                int row = m0 + m0w + mi * 16 + g + half * 8;
                size_t idx = (size_t)row * DM + col;
                C[idx]     = acc[mi][ni][half * 2 + 0] + bv0 + R[idx];
                C[idx + 1] = acc[mi][ni][half * 2 + 1] + bv1 + R[idx + 1];
            }
        }
    }
}

// ---------------- MoE GEMM 1 (tf32): gather + GELU ----------------
__global__ __launch_bounds__(256) void moe_gemm1_kernel(
    const float* __restrict__ X, const float* __restrict__ W1,
    const float* __restrict__ b1)
{
    int e = blockIdx.z;
    int M = g_cnt[e];
    int m0 = blockIdx.y * TBM;
    if (m0 >= M) return;
    const float* B = W1 + (size_t)e * DM * FF;
    const float* bias = b1 + (size_t)e * FF;
    float* C = g_h + (size_t)e * CAP * FF;
    const int* tl = g_tok + e * CAP;
    int n0 = blockIdx.x * TBN;

    PIPE_DECLS();
    int garow = m0 + car;
    int trow = (garow < M) ? tl[garow] : 0;
    int pa = (garow < M) ? 16 : 0;
    const float* asrc = X + (size_t)trow * DM + cac;
    const float* bsrc = B + n0 + cbc;
    const int ldb = FF;
    const int nkb = DM / KSTEP;

    PIPE_LOOP(frag_rn, pa);

#pragma unroll
    for (int mi = 0; mi < 4; mi++) {
#pragma unroll
        for (int ni = 0; ni < 4; ni++) {
            int col = n0 + n0w + ni * 8 + 2 * t;
            float bv0 = bias[col], bv1 = bias[col + 1];
#pragma unroll
            for (int half = 0; half < 2; half++) {
                int row = m0 + m0w + mi * 16 + g + half * 8;
                if (row >= M) continue;
                float v0 = acc[mi][ni][half * 2 + 0] + bv0;
                float v1 = acc[mi][ni][half * 2 + 1] + bv1;
                v0 = 0.5f * v0 * (1.f + erff(v0 * 0.70710678118654752f));
                v1 = 0.5f * v1 * (1.f + erff(v1 * 0.70710678118654752f));
                C[(size_t)row * FF + col]     = v0;
                C[(size_t)row * FF + col + 1] = v1;
            }
        }
    }
}

// ---------------- MoE GEMM 2 (tf32): * gate weight ----------------
__global__ __launch_bounds__(256) void moe_gemm2_kernel(
    const float* __restrict__ W2, const float* __restrict__ b2)
{
    int e = blockIdx.z;
    int M = g_cnt[e];
    int m0 = blockIdx.y * TBM;
    if (m0 >= M) return;
    const float* Ae = g_h + (size_t)e * CAP * FF;
    const float* B = W2 + (size_t)e * FF * DM;
    const float* bias = b2 + (size_t)e * DM;
    const float* wl = g_wl + e * CAP;
    float* C = g_eo + (size_t)e * CAP * DM;
    int n0 = blockIdx.x * TBN;

    PIPE_DECLS();
    int pa = (m0 + car < M) ? 16 : 0;
    const float* asrc = Ae + (size_t)(m0 + car) * FF + cac;
    const float* bsrc = B + n0 + cbc;
    const int ldb = DM;
    const int nkb = FF / KSTEP;

    PIPE_LOOP(frag_rn, pa);

#pragma unroll
    for (int mi = 0; mi < 4; mi++) {
#pragma unroll
        for (int ni = 0; ni < 4; ni++) {
            int col = n0 + n0w + ni * 8 + 2 * t;
            float bv0 = bias[col], bv1 = bias[col + 1];
#pragma unroll
            for (int half = 0; half < 2; half++) {
                int row = m0 + m0w + mi * 16 + g + half * 8;
                if (row >= M) continue;
                float wv = wl[row];
                C[(size_t)row * DM + col]     = (acc[mi][ni][half * 2 + 0] + bv0) * wv;
                C[(size_t)row * DM + col + 1] = (acc[mi][ni][half * 2 + 1] + bv1) * wv;
            }
        }
    }
}

// ---------------- fused sliding-window attention ----------------
#define APAD 68
__global__ __launch_bounds__(256) void attn_kernel(float* __restrict__ out)
{
    __shared__ float Qs[64][APAD];
    __shared__ float Ks[32][APAD];
    __shared__ float Vs[32][APAD];
    __shared__ float Ss[64][33];
    __shared__ float mS[64], lS[64], cS[64];

    int h = blockIdx.y;
    int q0 = blockIdx.x * 64;
    int tid = threadIdx.x;
    int q = tid & 63;
    int kg = tid >> 6;
    int dp = tid >> 6;

    const float* qhead = g_q + (size_t)h * SEQ * DH;
    const float* khead = g_k + (size_t)h * SEQ * DH;
    const float* vhead = g_v + (size_t)h * SEQ * DH;

#pragma unroll
    for (int i = 0; i < 4; i++) {
        int idx = tid + i * 256;
        int r = idx >> 4;
        int c = (idx & 15) << 2;
        float4 v = *(const float4*)&qhead[(size_t)(q0 + r) * DH + c];
        *(float4*)&Qs[r][c] = v;
    }
    if (tid < 64) { mS[tid] = -1e9f; lS[tid] = 0.f; }

    float acc[16];
#pragma unroll
    for (int i = 0; i < 16; i++) acc[i] = 0.f;
    __syncthreads();

    for (int kt = 0; kt < 18; kt++) {
        int kbase = q0 - 256 + kt * 32;
        if (kbase + 31 < 0 || kbase >= SEQ) continue;

#pragma unroll
        for (int i = 0; i < 2; i++) {
            int idx = tid + i * 256;
            int r = idx >> 4;
            int c = (idx & 15) << 2;
            int kpos = kbase + r;
            float4 kv = make_float4(0.f, 0.f, 0.f, 0.f);
            float4 vv = kv;
            if (kpos >= 0 && kpos < SEQ) {
                kv = *(const float4*)&khead[(size_t)kpos * DH + c];
                vv = *(const float4*)&vhead[(size_t)kpos * DH + c];
            }
            *(float4*)&Ks[r][c] = kv;
            *(float4*)&Vs[r][c] = vv;
        }
        __syncthreads();

        float s[8];
#pragma unroll
        for (int j = 0; j < 8; j++) s[j] = 0.f;
#pragma unroll
        for (int d = 0; d < 64; d += 4) {
            float4 q4 = *(const float4*)&Qs[q][d];
#pragma unroll
            for (int j = 0; j < 8; j++) {
                float4 k4 = *(const float4*)&Ks[kg * 8 + j][d];
                s[j] += q4.x * k4.x + q4.y * k4.y + q4.z * k4.z + q4.w * k4.w;
            }
        }
        int qpos = q0 + q;
#pragma unroll
        for (int j = 0; j < 8; j++) {
            int kpos = kbase + kg * 8 + j;
            bool valid = (kpos >= 0) && (kpos < SEQ) &&
                         (kpos >= qpos - WIN) && (kpos <= qpos + WIN);
            Ss[q][kg * 8 + j] = valid ? s[j] : -1e9f;
        }
        __syncthreads();

        if (tid < 64) {
            int r = tid;
            float mold = mS[r];
            float tmax = -1e9f;
#pragma unroll
            for (int kk = 0; kk < 32; kk++) tmax = fmaxf(tmax, Ss[r][kk]);
            float mnew = fmaxf(mold, tmax);
            float corr = __expf(mold - mnew);
            float sum = 0.f;
#pragma unroll
            for (int kk = 0; kk < 32; kk++) {
                float p = __expf(Ss[r][kk] - mnew);
                Ss[r][kk] = p;
                sum += p;
            }
            lS[r] = lS[r] * corr + sum;
            mS[r] = mnew;
            cS[r] = corr;
        }
        __syncthreads();

        float corr = cS[q];
#pragma unroll
        for (int i = 0; i < 16; i++) acc[i] *= corr;
#pragma unroll
        for (int kk = 0; kk < 32; kk++) {
            float p = Ss[q][kk];
#pragma unroll
            for (int i4 = 0; i4 < 4; i4++) {
                float4 v4 = *(const float4*)&Vs[kk][dp * 16 + i4 * 4];
                acc[i4 * 4 + 0] += p * v4.x;
                acc[i4 * 4 + 1] += p * v4.y;
                acc[i4 * 4 + 2] += p * v4.z;
                acc[i4 * 4 + 3] += p * v4.w;
            }
        }
        __syncthreads();
    }

    float inv = 1.f / lS[q];
    float* o = out + (size_t)(q0 + q) * DM + h * DH + dp * 16;
#pragma unroll
    for (int i4 = 0; i4 < 4; i4++) {
        float4 v;
        v.x = acc[i4 * 4 + 0] * inv;
        v.y = acc[i4 * 4 + 1] * inv;
        v.z = acc[i4 * 4 + 2] * inv;
        v.w = acc[i4 * 4 + 3] * inv;
        *(float4*)&o[i4 * 4] = v;
    }
}

// ---------------- layer norm (row-wise) ----------------
__global__ __launch_bounds__(256) void ln_kernel(
    const float* __restrict__ in, const float* __restrict__ g,
    const float* __restrict__ b, float* __restrict__ out)
{
    __shared__ float rs[8], rs2[8];
    int row = blockIdx.x;
    int tid = threadIdx.x;
    const float* x = in + (size_t)row * DM;
    float vals[3];
    float s = 0.f, s2 = 0.f;
#pragma unroll
    for (int i = 0; i < 3; i++) {
        float v = x[tid + i * 256];
        vals[i] = v;
        s += v;
        s2 += v * v;
    }
    int lane = tid & 31, w = tid >> 5;
#pragma unroll
    for (int o = 16; o; o >>= 1) {
        s += __shfl_down_sync(0xffffffffu, s, o);
        s2 += __shfl_down_sync(0xffffffffu, s2, o);
    }
    if (lane == 0) { rs[w] = s; rs2[w] = s2; }
    __syncthreads();
    if (tid == 0) {
        float a = 0.f, c = 0.f;
#pragma unroll
        for (int i = 0; i < 8; i++) { a += rs[i]; c += rs2[i]; }
        rs[0] = a;
        rs2[0] = c;
    }
    __syncthreads();
    float mean = rs[0] * (1.f / DM);
    float var = rs2[0] * (1.f / DM) - mean * mean;
    float rstd = rsqrtf(var + 1e-5f);
    float* o = out + (size_t)row * DM;
#pragma unroll
    for (int i = 0; i < 3; i++) {
        int col = tid + i * 256;
        o[col] = (vals[i] - mean) * rstd * g[col] + b[col];
    }
}

// ---------------- gating: logits, top-2, softmax, expert lists ----------------
__global__ __launch_bounds__(256) void gating_kernel(
    const float* __restrict__ x1, const float* __restrict__ gW,
    const float* __restrict__ gb, float* __restrict__ gate_out)
{
    __shared__ float xs[DM];
    __shared__ float lg[8];
    int row = blockIdx.x;
    int tid = threadIdx.x;
    for (int i = tid; i < DM; i += 256) xs[i] = x1[(size_t)row * DM + i];
    __syncthreads();
    int w = tid >> 5, lane = tid & 31;
    if (w < NE) {
        float p = 0.f;
        for (int d = lane; d < DM; d += 32) p += xs[d] * gW[d * NE + w];
#pragma unroll
        for (int o = 16; o; o >>= 1) p += __shfl_down_sync(0xffffffffu, p, o);
        if (lane == 0) lg[w] = p + gb[w];
    }
    __syncthreads();
    if (tid == 0) {
        int e1 = 0;
        float v1 = lg[0];
        for (int e = 1; e < NE; e++)
            if (lg[e] > v1) { v1 = lg[e]; e1 = e; }
        int e2 = -1;
        float v2 = -1e30f;
        for (int e = 0; e < NE; e++) {
            if (e == e1) continue;
            if (lg[e] > v2) { v2 = lg[e]; e2 = e; }
        }
        float z = expf(v2 - v1);
        float w1 = 1.f / (1.f + z);
        float w2 = z / (1.f + z);
        float* go = gate_out + (size_t)row * NE;
#pragma unroll
        for (int e = 0; e < NE; e++) go[e] = 0.f;
        go[e1] = w1;
        go[e2] = w2;
        int s1 = atomicAdd(&g_cnt[e1], 1);
        g_tok[e1 * CAP + s1] = row;
        g_wl[e1 * CAP + s1] = w1;
        g_pos[row * 2 + 0] = e1 * CAP + s1;
        int s2 = atomicAdd(&g_cnt[e2], 1);
        g_tok[e2 * CAP + s2] = row;
        g_wl[e2 * CAP + s2] = w2;
        g_pos[row * 2 + 1] = e2 * CAP + s2;
    }
}

// ---------------- combine two expert outputs per token ----------------
__global__ __launch_bounds__(192) void combine_kernel()
{
    int tk = blockIdx.x;
    int p0 = g_pos[tk * 2 + 0];
    int p1 = g_pos[tk * 2 + 1];
    const float* a = g_eo + (size_t)p0 * DM;
    const float* b = g_eo + (size_t)p1 * DM;
    float* o = g_moe + (size_t)tk * DM;
    int i = threadIdx.x * 4;
    float4 av = *(const float4*)&a[i];
    float4 bv = *(const float4*)&b[i];
    float4 v;
    v.x = av.x + bv.x;
    v.y = av.y + bv.y;
    v.z = av.z + bv.z;
    v.w = av.w + bv.w;
    *(float4*)&o[i] = v;
}

// ---------------- launch ----------------
extern "C" void kernel_launch(void* const* d_in, const int* in_sizes, int n_in,
                              void* d_out, int out_size)
{
    (void)in_sizes; (void)n_in; (void)out_size;
    const float* x     = (const float*)d_in[0];
    const float* Wq    = (const float*)d_in[1];
    const float* bq    = (const float*)d_in[2];
    const float* Wk    = (const float*)d_in[3];
    const float* bk    = (const float*)d_in[4];
    const float* Wv    = (const float*)d_in[5];
    const float* bv    = (const float*)d_in[6];
    const float* Wo    = (const float*)d_in[7];
    const float* bo    = (const float*)d_in[8];
    const float* ln1g  = (const float*)d_in[9];
    const float* ln1b  = (const float*)d_in[10];
    const float* gateW = (const float*)d_in[11];
    const float* gateb = (const float*)d_in[12];
    const float* W1e   = (const float*)d_in[13];
    const float* b1e   = (const float*)d_in[14];
    const float* W2e   = (const float*)d_in[15];
    const float* b2e   = (const float*)d_in[16];
    const float* Wd    = (const float*)d_in[17];
    const float* bd    = (const float*)d_in[18];
    const float* ln2g  = (const float*)d_in[19];
    const float* ln2b  = (const float*)d_in[20];

    float* out = (float*)d_out;
    float* gate_out = out + (size_t)SEQ * DM;

    float *pq, *pk, *pv, *pattno, *ptmp, *px1, *pmoe;
    cudaGetSymbolAddress((void**)&pq, g_q);
    cudaGetSymbolAddress((void**)&pk, g_k);
    cudaGetSymbolAddress((void**)&pv, g_v);
    cudaGetSymbolAddress((void**)&pattno, g_attno);
    cudaGetSymbolAddress((void**)&ptmp, g_tmp);
    cudaGetSymbolAddress((void**)&px1, g_x1);
    cudaGetSymbolAddress((void**)&pmoe, g_moe);

    reset_kernel<<<1, 32>>>();

    // QKV projections (tf32x3 ~ fp32 accuracy; q pre-scaled by 1/sqrt(64))
    qkv_x3_kernel<<<dim3(DM / TBN, SEQ / TBM, 3), 256>>>(
        x, Wq, Wk, Wv, bq, bk, bv, pq, pk, pv);

    // sliding-window attention (fp32)
    attn_kernel<<<dim3(SEQ / 64, NH), 256>>>(pattno);

    // Wo projection (tf32x3) + residual(hidden) -> LN1 -> x1
    gemm_x3_res_kernel<<<dim3(DM / TBN, SEQ / TBM), 256>>>(pattno, Wo, bo, ptmp, x, DM);
    ln_kernel<<<SEQ, 256>>>(ptmp, ln1g, ln1b, px1);

    // gating (fp32-exact; writes gate_weights output + expert lists)
    gating_kernel<<<SEQ, 256>>>(px1, gateW, gateb, gate_out);

    // MoE expert FFN (tf32 tensor cores, grouped sparse top-2)
    moe_gemm1_kernel<<<dim3(FF / TBN, CAP / TBM, NE), 256>>>(px1, W1e, b1e);
    moe_gemm2_kernel<<<dim3(DM / TBN, CAP / TBM, NE), 256>>>(W2e, b2e);
    combine_kernel<<<SEQ, 192>>>();

    // Wd projection (tf32) + residual(x1) -> LN2 -> layer_output
    gemm_rn_res_kernel<<<dim3(DM / TBN, SEQ / TBM), 256>>>(pmoe, Wd, bd, ptmp, px1, DM);
    ln_kernel<<<SEQ, 256>>>(ptmp, ln2g, ln2b, out);
}

// round 14
// speedup vs baseline: 1.4330x; 1.0372x over previous
#include <cuda_runtime.h>
#include <math.h>
#include <stdint.h>

#define SEQ 4096
#define DM  768
#define NH  12
#define DH  64
#define FF  3072
#define NE  7
#define WIN 256
#define CAP 4096

// ---------------- scratch (static device globals; no allocation) ----------------
__device__ float g_q[NH * SEQ * DH];
__device__ float g_k[NH * SEQ * DH];
__device__ float g_v[NH * SEQ * DH];
__device__ float g_attno[SEQ * DM];
__device__ float g_tmp[SEQ * DM];
__device__ float g_x1[SEQ * DM];
__device__ float g_moe[SEQ * DM];
__device__ float g_h[NE * CAP * FF];     // 352 MB
__device__ float g_eo[NE * CAP * DM];    // 88 MB
__device__ int   g_cnt[NE];
__device__ int   g_tok[NE * CAP];
__device__ float g_wl[NE * CAP];
__device__ int   g_pos[SEQ * 2];

// ---------------- reset ----------------
__global__ void reset_kernel() {
    if (threadIdx.x < NE) g_cnt[threadIdx.x] = 0;
}

// ======================================================================
// tf32 tensor-core GEMM, cp.async 4-stage pipeline + ldmatrix fragments
// BM=128, BN=128, KSTEP=8, 256 threads = 8 warps (2m x 4n), warp 64x32.
// smem holds raw fp32; tf32 conversion at fragment load (register cvt).
// 2 CTAs/SM for latency hiding.
// ======================================================================
#define TBM 128
#define TBN 128
#define KSTEP 8
#define NSTAGE 4
#define ASTR 12    // 8 + 4 pad: 48B rows, 16B-aligned, ldmatrix conflict-free
#define BSTR 136   // 128 + 8 pad: 8t+g hits all 32 banks -> conflict-free LDS

__device__ __forceinline__ unsigned f2tf(float f) {
    unsigned u;
    asm("cvt.rna.tf32.f32 %0, %1;" : "=r"(u) : "f"(f));
    return u;
}
__device__ __forceinline__ float f2tff(float f) {
    float h;
    asm("cvt.rna.tf32.f32 %0, %1;" : "=f"(h) : "f"(f));
    return h;
}

__device__ __forceinline__ void mma_tf32(float* c, const unsigned* a, const unsigned* b) {
    asm volatile(
        "mma.sync.aligned.m16n8k8.row.col.f32.tf32.tf32.f32 "
        "{%0,%1,%2,%3}, {%4,%5,%6,%7}, {%8,%9}, {%0,%1,%2,%3};"
        : "+f"(c[0]), "+f"(c[1]), "+f"(c[2]), "+f"(c[3])
        : "r"(a[0]), "r"(a[1]), "r"(a[2]), "r"(a[3]),
          "r"(b[0]), "r"(b[1]));
}

__device__ __forceinline__ void ldm_x4(unsigned* r, uint32_t addr) {
    asm volatile("ldmatrix.sync.aligned.m8n8.x4.shared.b16 {%0,%1,%2,%3}, [%4];"
                 : "=r"(r[0]), "=r"(r[1]), "=r"(r[2]), "=r"(r[3]) : "r"(addr));
}

__device__ __forceinline__ void cp16(uint32_t dst, const void* src, int sz) {
    asm volatile("cp.async.cg.shared.global [%0], [%1], 16, %2;"
                 :: "r"(dst), "l"(src), "r"(sz) : "memory");
}
__device__ __forceinline__ void cp_commit() {
    asm volatile("cp.async.commit_group;" ::: "memory");
}
__device__ __forceinline__ void cp_wait2() {
    asm volatile("cp.async.wait_group 2;" ::: "memory");
}
__device__ __forceinline__ uint32_t smem_u32(const void* p) {
    return (uint32_t)__cvta_generic_to_shared(p);
}

// single-MMA tf32 (RN conversion in registers after ldmatrix)
__device__ __forceinline__ void frag_rn(
    const float (*As_)[ASTR], const float (*Bs_)[BSTR],
    float acc[4][4][4], int a_row, int a_col, int n0w, int g, int t)
{
    uint32_t ab = smem_u32(&As_[a_row][a_col]);
    unsigned a_[4][4];
#pragma unroll
    for (int mi = 0; mi < 4; mi++) ldm_x4(a_[mi], ab + mi * 16 * ASTR * 4);
#pragma unroll
    for (int mi = 0; mi < 4; mi++)
#pragma unroll
        for (int j = 0; j < 4; j++)
            a_[mi][j] = f2tf(__uint_as_float(a_[mi][j]));

    unsigned b_[4][2];
#pragma unroll
    for (int ni = 0; ni < 4; ni++) {
        int nb = n0w + ni * 8 + g;
        b_[ni][0] = f2tf(Bs_[t][nb]);
        b_[ni][1] = f2tf(Bs_[t + 4][nb]);
    }
#pragma unroll
    for (int mi = 0; mi < 4; mi++)
#pragma unroll
        for (int ni = 0; ni < 4; ni++)
            mma_tf32(acc[mi][ni], a_[mi], b_[ni]);
}

// tf32x3 error-compensated (~fp32): hi*hi + lo*hi + hi*lo
__device__ __forceinline__ void frag_x3(
    const float (*As_)[ASTR], const float (*Bs_)[BSTR],
    float acc[4][4][4], int a_row, int a_col, int n0w, int g, int t)
{
    uint32_t ab = smem_u32(&As_[a_row][a_col]);
    unsigned araw[4][4];
#pragma unroll
    for (int mi = 0; mi < 4; mi++) ldm_x4(araw[mi], ab + mi * 16 * ASTR * 4);

    unsigned ahi[4][4], alo[4][4], bhi[4][2], blo[4][2];
#pragma unroll
    for (int mi = 0; mi < 4; mi++)
#pragma unroll
        for (int j = 0; j < 4; j++) {
            float f = __uint_as_float(araw[mi][j]);
            float h = f2tff(f);
            ahi[mi][j] = __float_as_uint(h);
            alo[mi][j] = __float_as_uint(f - h);
        }
#pragma unroll
    for (int ni = 0; ni < 4; ni++) {
        int nb = n0w + ni * 8 + g;
        float bv[2] = {Bs_[t][nb], Bs_[t + 4][nb]};
#pragma unroll
        for (int j = 0; j < 2; j++) {
            float h = f2tff(bv[j]);
            bhi[ni][j] = __float_as_uint(h);
            blo[ni][j] = __float_as_uint(bv[j] - h);
        }
    }
#pragma unroll
    for (int mi = 0; mi < 4; mi++)
#pragma unroll
        for (int ni = 0; ni < 4; ni++) {
            mma_tf32(acc[mi][ni], alo[mi], bhi[ni]);
            mma_tf32(acc[mi][ni], ahi[mi], blo[ni]);
            mma_tf32(acc[mi][ni], ahi[mi], bhi[ni]);
        }
}

#define PIPE_DECLS()                                                       \
    __shared__ __align__(16) float As[NSTAGE][TBM][ASTR];                  \
    __shared__ __align__(16) float Bs[NSTAGE][KSTEP][BSTR];                \
    int tid = threadIdx.x;                                                 \
    int car = tid >> 1, cac = (tid & 1) * 4;                               \
    int cbr = tid >> 5, cbc = (tid & 31) * 4;                              \
    int w = tid >> 5, lane = tid & 31;                                     \
    int m0w = (w >> 2) * 64, n0w = (w & 3) * 32;                           \
    int g = lane >> 2, t = lane & 3;                                       \
    int a_row = m0w + (lane & 7) + ((lane >> 3) & 1) * 8;                  \
    int a_col = (lane >> 4) * 4;                                           \
    float acc[4][4][4];                                                    \
    _Pragma("unroll")                                                      \
    for (int mi = 0; mi < 4; mi++)                                         \
        _Pragma("unroll")                                                  \
        for (int ni = 0; ni < 4; ni++)                                     \
            _Pragma("unroll")                                              \
            for (int j = 0; j < 4; j++) acc[mi][ni][j] = 0.f;

// issue one stage: A row chunk + B row chunk, then commit
#define PIPE_ISSUE(s, k0, pz, pa)                                          \
    cp16(smem_u32(&As[s][car][cac]), asrc + (k0), ((pz) & (pa)));          \
    cp16(smem_u32(&Bs[s][cbr][cbc]), bsrc + (size_t)((k0) + cbr) * ldb, (pz)); \
    cp_commit();

// 4-stage: prologue fills 0..2; steady state waits oldest (<=2 pending),
// syncs (all warps done with stage (kb-1)%4), issues kb+3 into that slot.
#define PIPE_LOOP(FRAG, pa)                                                \
    PIPE_ISSUE(0, 0, 16, pa);                                              \
    PIPE_ISSUE(1, KSTEP, 16, pa);                                          \
    PIPE_ISSUE(2, 2 * KSTEP, 16, pa);                                      \
    for (int kb = 0; kb < nkb; kb++) {                                     \
        cp_wait2();                                                        \
        __syncthreads();                                                   \
        int k3 = (kb + 3) * KSTEP;                                         \
        int s3 = (kb + 3) & 3;                                             \
        int pz = (kb + 3 < nkb) ? 16 : 0;                                  \
        PIPE_ISSUE(s3, k3, pz, pa);                                        \
        FRAG(As[kb & 3], Bs[kb & 3], acc, a_row, a_col, n0w, g, t);        \
    }

// ---------------- QKV (tf32x3, fp32-accurate): head-scatter epilogue ----------------
__global__ __launch_bounds__(256, 2) void qkv_x3_kernel(
    const float* __restrict__ A,
    const float* __restrict__ W0, const float* __restrict__ W1, const float* __restrict__ W2,
    const float* __restrict__ b0, const float* __restrict__ b1, const float* __restrict__ b2,
    float* __restrict__ C0, float* __restrict__ C1, float* __restrict__ C2)
{
    int which = blockIdx.z;
    const float* B    = which == 0 ? W0 : (which == 1 ? W1 : W2);
    const float* bias = which == 0 ? b0 : (which == 1 ? b1 : b2);
    float* C          = which == 0 ? C0 : (which == 1 ? C1 : C2);
    float scale       = which == 0 ? 0.125f : 1.0f;
    int m0 = blockIdx.y * TBM;
    int n0 = blockIdx.x * TBN;

    PIPE_DECLS();
    const float* asrc = A + (size_t)(m0 + car) * DM + cac;
    const float* bsrc = B + n0 + cbc;
    const int ldb = DM;
    const int nkb = DM / KSTEP;

    PIPE_LOOP(frag_x3, 16);

#pragma unroll
    for (int mi = 0; mi < 4; mi++) {
#pragma unroll
        for (int ni = 0; ni < 4; ni++) {
            int col = n0 + n0w + ni * 8 + 2 * t;
            float bv0 = bias[col], bv1 = bias[col + 1];
#pragma unroll
            for (int half = 0; half < 2; half++) {
                int row = m0 + m0w + mi * 16 + g + half * 8;
                float v0 = (acc[mi][ni][half * 2 + 0] + bv0) * scale;
                float v1 = (acc[mi][ni][half * 2 + 1] + bv1) * scale;
                C[((size_t)(col >> 6) * SEQ + row) * 64 + (col & 63)]       = v0;
                C[((size_t)((col + 1) >> 6) * SEQ + row) * 64 + ((col + 1) & 63)] = v1;
            }
        }
    }
}

// ---------------- Wo (tf32x3, fp32-accurate): + bias + residual ----------------
__global__ __launch_bounds__(256, 2) void gemm_x3_res_kernel(
    const float* __restrict__ A, const float* __restrict__ B,
    const float* __restrict__ bias, float* __restrict__ C,
    const float* __restrict__ R, int K)
{
    int m0 = blockIdx.y * TBM;
    int n0 = blockIdx.x * TBN;

    PIPE_DECLS();
    const float* asrc = A + (size_t)(m0 + car) * K + cac;
    const float* bsrc = B + n0 + cbc;
    const int ldb = DM;
    const int nkb = K / KSTEP;

    PIPE_LOOP(frag_x3, 16);

#pragma unroll
    for (int mi = 0; mi < 4; mi++) {
#pragma unroll
        for (int ni = 0; ni < 4; ni++) {
            int col = n0 + n0w + ni * 8 + 2 * t;
            float bv0 = bias[col], bv1 = bias[col + 1];
#pragma unroll
            for (int half = 0; half < 2; half++) {
                int row = m0 + m0w + mi * 16 + g + half * 8;
                size_t idx = (size_t)row * DM + col;
                C[idx]     = acc[mi][ni][half * 2 + 0] + bv0 + R[idx];
                C[idx + 1] = acc[mi][ni][half * 2 + 1] + bv1 + R[idx + 1];
            }
        }
    }
}

// ---------------- Wd (tf32): + bias + residual ----------------
__global__ __launch_bounds__(256, 2) void gemm_rn_res_kernel(
    const float* __restrict__ A, const float* __restrict__ B,
    const float* __restrict__ bias, float* __restrict__ C,
    const float* __restrict__ R, int K)
{
    int m0 = blockIdx.y * TBM;
    int n0 = blockIdx.x * TBN;

    PIPE_DECLS();
    const float* asrc = A + (size_t)(m0 + car) * K + cac;
    const float* bsrc = B + n0 + cbc;
    const int ldb = DM;
    const int nkb = K / KSTEP;

    PIPE_LOOP(frag_rn, 16);

#pragma unroll
    for (int mi = 0; mi < 4; mi++) {
#pragma unroll
        for (int ni = 0; ni < 4; ni++) {
            int col = n0 + n0w + ni * 8 + 2 * t;
            float bv0 = bias[col], bv1 = bias[col + 1];
#pragma unroll
            for (int half = 0; half < 2; half++) {
                int row = m0 + m0w + mi * 16 + g + half * 8;
                size_t idx = (size_t)row * DM + col;
                C[idx]     = acc[mi][ni][half * 2 + 0] + bv0 + R[idx];
                C[idx + 1] = acc[mi][ni][half * 2 + 1] + bv1 + R[idx + 1];
            }
        }
    }
}

// ---------------- MoE GEMM 1 (tf32): gather + GELU ----------------
__global__ __launch_bounds__(256, 2) void moe_gemm1_kernel(
    const float* __restrict__ X, const float* __restrict__ W1,
    const float* __restrict__ b1)
{
    int e = blockIdx.z;
    int M = g_cnt[e];
    int m0 = blockIdx.y * TBM;
    if (m0 >= M) return;
    const float* B = W1 + (size_t)e * DM * FF;
    const float* bias = b1 + (size_t)e * FF;
    float* C = g_h + (size_t)e * CAP * FF;
    const int* tl = g_tok + e * CAP;
    int n0 = blockIdx.x * TBN;

    PIPE_DECLS();
    int garow = m0 + car;
    int trow = (garow < M) ? tl[garow] : 0;
    int pa = (garow < M) ? 16 : 0;
    const float* asrc = X + (size_t)trow * DM + cac;
    const float* bsrc = B + n0 + cbc;
    const int ldb = FF;
    const int nkb = DM / KSTEP;

    PIPE_LOOP(frag_rn, pa);

#pragma unroll
    for (int mi = 0; mi < 4; mi++) {
#pragma unroll
        for (int ni = 0; ni < 4; ni++) {
            int col = n0 + n0w + ni * 8 + 2 * t;
            float bv0 = bias[col], bv1 = bias[col + 1];
#pragma unroll
            for (int half = 0; half < 2; half++) {
                int row = m0 + m0w + mi * 16 + g + half * 8;
                if (row >= M) continue;
                float v0 = acc[mi][ni][half * 2 + 0] + bv0;
                float v1 = acc[mi][ni][half * 2 + 1] + bv1;
                v0 = 0.5f * v0 * (1.f + erff(v0 * 0.70710678118654752f));
                v1 = 0.5f * v1 * (1.f + erff(v1 * 0.70710678118654752f));
                C[(size_t)row * FF + col]     = v0;
                C[(size_t)row * FF + col + 1] = v1;
            }
        }
    }
}

// ---------------- MoE GEMM 2 (tf32): * gate weight ----------------
__global__ __launch_bounds__(256, 2) void moe_gemm2_kernel(
    const float* __restrict__ W2, const float* __restrict__ b2)
{
    int e = blockIdx.z;
    int M = g_cnt[e];
    int m0 = blockIdx.y * TBM;
    if (m0 >= M) return;
    const float* Ae = g_h + (size_t)e * CAP * FF;
    const float* B = W2 + (size_t)e * FF * DM;
    const float* bias = b2 + (size_t)e * DM;
    const float* wl = g_wl + e * CAP;
    float* C = g_eo + (size_t)e * CAP * DM;
    int n0 = blockIdx.x * TBN;

    PIPE_DECLS();
    int pa = (m0 + car < M) ? 16 : 0;
    const float* asrc = Ae + (size_t)(m0 + car) * FF + cac;
    const float* bsrc = B + n0 + cbc;
    const int ldb = DM;
    const int nkb = FF / KSTEP;

    PIPE_LOOP(frag_rn, pa);

#pragma unroll
    for (int mi = 0; mi < 4; mi++) {
#pragma unroll
        for (int ni = 0; ni < 4; ni++) {
            int col = n0 + n0w + ni * 8 + 2 * t;
            float bv0 = bias[col], bv1 = bias[col + 1];
#pragma unroll
            for (int half = 0; half < 2; half++) {
                int row = m0 + m0w + mi * 16 + g + half * 8;
                if (row >= M) continue;
                float wv = wl[row];
                C[(size_t)row * DM + col]     = (acc[mi][ni][half * 2 + 0] + bv0) * wv;
                C[(size_t)row * DM + col + 1] = (acc[mi][ni][half * 2 + 1] + bv1) * wv;
            }
        }
    }
}

// ---------------- fused sliding-window attention ----------------
#define APAD 68
__global__ __launch_bounds__(256) void attn_kernel(float* __restrict__ out)
{
    __shared__ float Qs[64][APAD];
    __shared__ float Ks[32][APAD];
    __shared__ float Vs[32][APAD];
    __shared__ float Ss[64][33];
    __shared__ float mS[64], lS[64], cS[64];

    int h = blockIdx.y;
    int q0 = blockIdx.x * 64;
    int tid = threadIdx.x;
    int q = tid & 63;
    int kg = tid >> 6;
    int dp = tid >> 6;

    const float* qhead = g_q + (size_t)h * SEQ * DH;
    const float* khead = g_k + (size_t)h * SEQ * DH;
    const float* vhead = g_v + (size_t)h * SEQ * DH;

#pragma unroll
    for (int i = 0; i < 4; i++) {
        int idx = tid + i * 256;
        int r = idx >> 4;
        int c = (idx & 15) << 2;
        float4 v = *(const float4*)&qhead[(size_t)(q0 + r) * DH + c];
        *(float4*)&Qs[r][c] = v;
    }
    if (tid < 64) { mS[tid] = -1e9f; lS[tid] = 0.f; }

    float acc[16];
#pragma unroll
    for (int i = 0; i < 16; i++) acc[i] = 0.f;
    __syncthreads();

    for (int kt = 0; kt < 18; kt++) {
        int kbase = q0 - 256 + kt * 32;
        if (kbase + 31 < 0 || kbase >= SEQ) continue;

#pragma unroll
        for (int i = 0; i < 2; i++) {
            int idx = tid + i * 256;
            int r = idx >> 4;
            int c = (idx & 15) << 2;
            int kpos = kbase + r;
            float4 kv = make_float4(0.f, 0.f, 0.f, 0.f);
            float4 vv = kv;
            if (kpos >= 0 && kpos < SEQ) {
                kv = *(const float4*)&khead[(size_t)kpos * DH + c];
                vv = *(const float4*)&vhead[(size_t)kpos * DH + c];
            }
            *(float4*)&Ks[r][c] = kv;
            *(float4*)&Vs[r][c] = vv;
        }
        __syncthreads();

        float s[8];
#pragma unroll
        for (int j = 0; j < 8; j++) s[j] = 0.f;
#pragma unroll
        for (int d = 0; d < 64; d += 4) {
            float4 q4 = *(const float4*)&Qs[q][d];
#pragma unroll
            for (int j = 0; j < 8; j++) {
                float4 k4 = *(const float4*)&Ks[kg * 8 + j][d];
                s[j] += q4.x * k4.x + q4.y * k4.y + q4.z * k4.z + q4.w * k4.w;
            }
        }
        int qpos = q0 + q;
#pragma unroll
        for (int j = 0; j < 8; j++) {
            int kpos = kbase + kg * 8 + j;
            bool valid = (kpos >= 0) && (kpos < SEQ) &&
                         (kpos >= qpos - WIN) && (kpos <= qpos + WIN);
            Ss[q][kg * 8 + j] = valid ? s[j] : -1e9f;
        }
        __syncthreads();

        if (tid < 64) {
            int r = tid;
            float mold = mS[r];
            float tmax = -1e9f;
#pragma unroll
            for (int kk = 0; kk < 32; kk++) tmax = fmaxf(tmax, Ss[r][kk]);
            float mnew = fmaxf(mold, tmax);
            float corr = __expf(mold - mnew);
            float sum = 0.f;
#pragma unroll
            for (int kk = 0; kk < 32; kk++) {
                float p = __expf(Ss[r][kk] - mnew);
                Ss[r][kk] = p;
                sum += p;
            }
            lS[r] = lS[r] * corr + sum;
            mS[r] = mnew;
            cS[r] = corr;
        }
        __syncthreads();

        float corr = cS[q];
#pragma unroll
        for (int i = 0; i < 16; i++) acc[i] *= corr;
#pragma unroll
        for (int kk = 0; kk < 32; kk++) {
            float p = Ss[q][kk];
#pragma unroll
            for (int i4 = 0; i4 < 4; i4++) {
                float4 v4 = *(const float4*)&Vs[kk][dp * 16 + i4 * 4];
                acc[i4 * 4 + 0] += p * v4.x;
                acc[i4 * 4 + 1] += p * v4.y;
                acc[i4 * 4 + 2] += p * v4.z;
                acc[i4 * 4 + 3] += p * v4.w;
            }
        }
        __syncthreads();
    }

    float inv = 1.f / lS[q];
    float* o = out + (size_t)(q0 + q) * DM + h * DH + dp * 16;
#pragma unroll
    for (int i4 = 0; i4 < 4; i4++) {
        float4 v;
        v.x = acc[i4 * 4 + 0] * inv;
        v.y = acc[i4 * 4 + 1] * inv;
        v.z = acc[i4 * 4 + 2] * inv;
        v.w = acc[i4 * 4 + 3] * inv;
        *(float4*)&o[i4 * 4] = v;
    }
}

// ---------------- layer norm (row-wise) ----------------
__global__ __launch_bounds__(256) void ln_kernel(
    const float* __restrict__ in, const float* __restrict__ g,
    const float* __restrict__ b, float* __restrict__ out)
{
    __shared__ float rs[8], rs2[8];
    int row = blockIdx.x;
    int tid = threadIdx.x;
    const float* x = in + (size_t)row * DM;
    float vals[3];
    float s = 0.f, s2 = 0.f;
#pragma unroll
    for (int i = 0; i < 3; i++) {
        float v = x[tid + i * 256];
        vals[i] = v;
        s += v;
        s2 += v * v;
    }
    int lane = tid & 31, w = tid >> 5;
#pragma unroll
    for (int o = 16; o; o >>= 1) {
        s += __shfl_down_sync(0xffffffffu, s, o);
        s2 += __shfl_down_sync(0xffffffffu, s2, o);
    }
    if (lane == 0) { rs[w] = s; rs2[w] = s2; }
    __syncthreads();
    if (tid == 0) {
        float a = 0.f, c = 0.f;
#pragma unroll
        for (int i = 0; i < 8; i++) { a += rs[i]; c += rs2[i]; }
        rs[0] = a;
        rs2[0] = c;
    }
    __syncthreads();
    float mean = rs[0] * (1.f / DM);
    float var = rs2[0] * (1.f / DM) - mean * mean;
    float rstd = rsqrtf(var + 1e-5f);
    float* o = out + (size_t)row * DM;
#pragma unroll
    for (int i = 0; i < 3; i++) {
        int col = tid + i * 256;
        o[col] = (vals[i] - mean) * rstd * g[col] + b[col];
    }
}

// ---------------- gating: logits, top-2, softmax, expert lists ----------------
__global__ __launch_bounds__(256) void gating_kernel(
    const float* __restrict__ x1, const float* __restrict__ gW,
    const float* __restrict__ gb, float* __restrict__ gate_out)
{
    __shared__ float xs[DM];
    __shared__ float lg[8];
    int row = blockIdx.x;
    int tid = threadIdx.x;
    for (int i = tid; i < DM; i += 256) xs[i] = x1[(size_t)row * DM + i];
    __syncthreads();
    int w = tid >> 5, lane = tid & 31;
    if (w < NE) {
        float p = 0.f;
        for (int d = lane; d < DM; d += 32) p += xs[d] * gW[d * NE + w];
#pragma unroll
        for (int o = 16; o; o >>= 1) p += __shfl_down_sync(0xffffffffu, p, o);
        if (lane == 0) lg[w] = p + gb[w];
    }
    __syncthreads();
    if (tid == 0) {
        int e1 = 0;
        float v1 = lg[0];
        for (int e = 1; e < NE; e++)
            if (lg[e] > v1) { v1 = lg[e]; e1 = e; }
        int e2 = -1;
        float v2 = -1e30f;
        for (int e = 0; e < NE; e++) {
            if (e == e1) continue;
            if (lg[e] > v2) { v2 = lg[e]; e2 = e; }
        }
        float z = expf(v2 - v1);
        float w1 = 1.f / (1.f + z);
        float w2 = z / (1.f + z);
        float* go = gate_out + (size_t)row * NE;
#pragma unroll
        for (int e = 0; e < NE; e++) go[e] = 0.f;
        go[e1] = w1;
        go[e2] = w2;
        int s1 = atomicAdd(&g_cnt[e1], 1);
        g_tok[e1 * CAP + s1] = row;
        g_wl[e1 * CAP + s1] = w1;
        g_pos[row * 2 + 0] = e1 * CAP + s1;
        int s2 = atomicAdd(&g_cnt[e2], 1);
        g_tok[e2 * CAP + s2] = row;
        g_wl[e2 * CAP + s2] = w2;
        g_pos[row * 2 + 1] = e2 * CAP + s2;
    }
}

// ---------------- combine two expert outputs per token ----------------
__global__ __launch_bounds__(192) void combine_kernel()
{
    int tk = blockIdx.x;
    int p0 = g_pos[tk * 2 + 0];
    int p1 = g_pos[tk * 2 + 1];
    const float* a = g_eo + (size_t)p0 * DM;
    const float* b = g_eo + (size_t)p1 * DM;
    float* o = g_moe + (size_t)tk * DM;
    int i = threadIdx.x * 4;
    float4 av = *(const float4*)&a[i];
    float4 bv = *(const float4*)&b[i];
    float4 v;
    v.x = av.x + bv.x;
    v.y = av.y + bv.y;
    v.z = av.z + bv.z;
    v.w = av.w + bv.w;
    *(float4*)&o[i] = v;
}

// ---------------- launch ----------------
extern "C" void kernel_launch(void* const* d_in, const int* in_sizes, int n_in,
                              void* d_out, int out_size)
{
    (void)in_sizes; (void)n_in; (void)out_size;
    const float* x     = (const float*)d_in[0];
    const float* Wq    = (const float*)d_in[1];
    const float* bq    = (const float*)d_in[2];
    const float* Wk    = (const float*)d_in[3];
    const float* bk    = (const float*)d_in[4];
    const float* Wv    = (const float*)d_in[5];
    const float* bv    = (const float*)d_in[6];
    const float* Wo    = (const float*)d_in[7];
    const float* bo    = (const float*)d_in[8];
    const float* ln1g  = (const float*)d_in[9];
    const float* ln1b  = (const float*)d_in[10];
    const float* gateW = (const float*)d_in[11];
    const float* gateb = (const float*)d_in[12];
    const float* W1e   = (const float*)d_in[13];
    const float* b1e   = (const float*)d_in[14];
    const float* W2e   = (const float*)d_in[15];
    const float* b2e   = (const float*)d_in[16];
    const float* Wd    = (const float*)d_in[17];
    const float* bd    = (const float*)d_in[18];
    const float* ln2g  = (const float*)d_in[19];
    const float* ln2b  = (const float*)d_in[20];

    float* out = (float*)d_out;
    float* gate_out = out + (size_t)SEQ * DM;

    float *pq, *pk, *pv, *pattno, *ptmp, *px1, *pmoe;
    cudaGetSymbolAddress((void**)&pq, g_q);
    cudaGetSymbolAddress((void**)&pk, g_k);
    cudaGetSymbolAddress((void**)&pv, g_v);
    cudaGetSymbolAddress((void**)&pattno, g_attno);
    cudaGetSymbolAddress((void**)&ptmp, g_tmp);
    cudaGetSymbolAddress((void**)&px1, g_x1);
    cudaGetSymbolAddress((void**)&pmoe, g_moe);

    reset_kernel<<<1, 32>>>();

    // QKV projections (tf32x3 ~ fp32 accuracy; q pre-scaled by 1/sqrt(64))
    qkv_x3_kernel<<<dim3(DM / TBN, SEQ / TBM, 3), 256>>>(
        x, Wq, Wk, Wv, bq, bk, bv, pq, pk, pv);

    // sliding-window attention (fp32)
    attn_kernel<<<dim3(SEQ / 64, NH), 256>>>(pattno);

    // Wo projection (tf32x3) + residual(hidden) -> LN1 -> x1
    gemm_x3_res_kernel<<<dim3(DM / TBN, SEQ / TBM), 256>>>(pattno, Wo, bo, ptmp, x, DM);
    ln_kernel<<<SEQ, 256>>>(ptmp, ln1g, ln1b, px1);

    // gating (fp32-exact; writes gate_weights output + expert lists)
    gating_kernel<<<SEQ, 256>>>(px1, gateW, gateb, gate_out);

    // MoE expert FFN (tf32 tensor cores, grouped sparse top-2)
    moe_gemm1_kernel<<<dim3(FF / TBN, CAP / TBM, NE), 256>>>(px1, W1e, b1e);
    moe_gemm2_kernel<<<dim3(DM / TBN, CAP / TBM, NE), 256>>>(W2e, b2e);
    combine_kernel<<<SEQ, 192>>>();

    // Wd projection (tf32) + residual(x1) -> LN2 -> layer_output
    gemm_rn_res_kernel<<<dim3(DM / TBN, SEQ / TBM), 256>>>(pmoe, Wd, bd, ptmp, px1, DM);
    ln_kernel<<<SEQ, 256>>>(ptmp, ln2g, ln2b, out);
}

// round 15
// speedup vs baseline: 1.5002x; 1.0469x over previous
#include <cuda_runtime.h>
#include <math.h>
#include <stdint.h>

#define SEQ 4096
#define DM  768
#define NH  12
#define DH  64
#define FF  3072
#define NE  7
#define WIN 256
#define CAP 4096

// ---------------- scratch (static device globals; no allocation) ----------------
__device__ float g_q[NH * SEQ * DH];
__device__ float g_k[NH * SEQ * DH];
__device__ float g_v[NH * SEQ * DH];
__device__ float g_attno[SEQ * DM];
__device__ float g_tmp[SEQ * DM];
__device__ float g_x1[SEQ * DM];
__device__ float g_x1r[SEQ * DM];        // tf32-rounded copy (MoE A operand)
__device__ float g_moe[SEQ * DM];
__device__ float g_part[2 * SEQ * DM];   // split-K partials
__device__ float g_h[NE * CAP * FF];     // 352 MB
__device__ float g_eo[NE * CAP * DM];    // 88 MB
__device__ int   g_cnt[NE];
__device__ int   g_tok[NE * CAP];
__device__ float g_wl[NE * CAP];
__device__ int   g_pos[SEQ * 2];

// ---------------- reset ----------------
__global__ void reset_kernel() {
    if (threadIdx.x < NE) g_cnt[threadIdx.x] = 0;
}

// ======================================================================
// tf32 tensor-core GEMM, cp.async 4-stage pipeline + ldmatrix fragments
// BM=128, BN=128, KSTEP=8, 256 threads = 8 warps (2m x 4n), warp 64x32.
// rn path: A pre-rounded to tf32 values in gmem -> raw fragment bits.
// ======================================================================
#define TBM 128
#define TBN 128
#define KSTEP 8
#define NSTAGE 4
#define ASTR 12    // 8 + 4 pad: 48B rows, 16B-aligned, ldmatrix conflict-free
#define BSTR 136   // 128 + 8 pad: 8t+g hits all 32 banks -> conflict-free LDS

__device__ __forceinline__ unsigned f2tf(float f) {
    unsigned u;
    asm("cvt.rna.tf32.f32 %0, %1;" : "=r"(u) : "f"(f));
    return u;
}
__device__ __forceinline__ float f2tff(float f) {
    float h;
    asm("cvt.rna.tf32.f32 %0, %1;" : "=f"(h) : "f"(f));
    return h;
}

__device__ __forceinline__ void mma_tf32(float* c, const unsigned* a, const unsigned* b) {
    asm volatile(
        "mma.sync.aligned.m16n8k8.row.col.f32.tf32.tf32.f32 "
        "{%0,%1,%2,%3}, {%4,%5,%6,%7}, {%8,%9}, {%0,%1,%2,%3};"
        : "+f"(c[0]), "+f"(c[1]), "+f"(c[2]), "+f"(c[3])
        : "r"(a[0]), "r"(a[1]), "r"(a[2]), "r"(a[3]),
          "r"(b[0]), "r"(b[1]));
}

__device__ __forceinline__ void ldm_x4(unsigned* r, uint32_t addr) {
    asm volatile("ldmatrix.sync.aligned.m8n8.x4.shared.b16 {%0,%1,%2,%3}, [%4];"
                 : "=r"(r[0]), "=r"(r[1]), "=r"(r[2]), "=r"(r[3]) : "r"(addr));
}

__device__ __forceinline__ void cp16(uint32_t dst, const void* src, int sz) {
    asm volatile("cp.async.cg.shared.global [%0], [%1], 16, %2;"
                 :: "r"(dst), "l"(src), "r"(sz) : "memory");
}
__device__ __forceinline__ void cp_commit() {
    asm volatile("cp.async.commit_group;" ::: "memory");
}
__device__ __forceinline__ void cp_wait2() {
    asm volatile("cp.async.wait_group 2;" ::: "memory");
}
__device__ __forceinline__ uint32_t smem_u32(const void* p) {
    return (uint32_t)__cvta_generic_to_shared(p);
}

// rn path: A data is pre-rounded to tf32 values -> use raw bits (bit-identical
// to f2tf at load). B converted with RNA in registers (8 cvts/k-step).
__device__ __forceinline__ void frag_rn(
    const float (*As_)[ASTR], const float (*Bs_)[BSTR],
    float acc[4][4][4], int a_row, int a_col, int n0w, int g, int t)
{
    uint32_t ab = smem_u32(&As_[a_row][a_col]);
    unsigned a_[4][4];
#pragma unroll
    for (int mi = 0; mi < 4; mi++) ldm_x4(a_[mi], ab + mi * 16 * ASTR * 4);

    unsigned b_[4][2];
#pragma unroll
    for (int ni = 0; ni < 4; ni++) {
        int nb = n0w + ni * 8 + g;
        b_[ni][0] = f2tf(Bs_[t][nb]);
        b_[ni][1] = f2tf(Bs_[t + 4][nb]);
    }
#pragma unroll
    for (int mi = 0; mi < 4; mi++)
#pragma unroll
        for (int ni = 0; ni < 4; ni++)
            mma_tf32(acc[mi][ni], a_[mi], b_[ni]);
}

// tf32x3 error-compensated (~fp32): hi*hi + lo*hi + hi*lo
__device__ __forceinline__ void frag_x3(
    const float (*As_)[ASTR], const float (*Bs_)[BSTR],
    float acc[4][4][4], int a_row, int a_col, int n0w, int g, int t)
{
    uint32_t ab = smem_u32(&As_[a_row][a_col]);
    unsigned araw[4][4];
#pragma unroll
    for (int mi = 0; mi < 4; mi++) ldm_x4(araw[mi], ab + mi * 16 * ASTR * 4);

    unsigned ahi[4][4], alo[4][4], bhi[4][2], blo[4][2];
#pragma unroll
    for (int mi = 0; mi < 4; mi++)
#pragma unroll
        for (int j = 0; j < 4; j++) {
            float f = __uint_as_float(araw[mi][j]);
            float h = f2tff(f);
            ahi[mi][j] = __float_as_uint(h);
            alo[mi][j] = __float_as_uint(f - h);
        }
#pragma unroll
    for (int ni = 0; ni < 4; ni++) {
        int nb = n0w + ni * 8 + g;
        float bv[2] = {Bs_[t][nb], Bs_[t + 4][nb]};
#pragma unroll
        for (int j = 0; j < 2; j++) {
            float h = f2tff(bv[j]);
            bhi[ni][j] = __float_as_uint(h);
            blo[ni][j] = __float_as_uint(bv[j] - h);
        }
    }
#pragma unroll
    for (int mi = 0; mi < 4; mi++)
#pragma unroll
        for (int ni = 0; ni < 4; ni++) {
            mma_tf32(acc[mi][ni], alo[mi], bhi[ni]);
            mma_tf32(acc[mi][ni], ahi[mi], blo[ni]);
            mma_tf32(acc[mi][ni], ahi[mi], bhi[ni]);
        }
}

#define PIPE_DECLS()                                                       \
    __shared__ __align__(16) float As[NSTAGE][TBM][ASTR];                  \
    __shared__ __align__(16) float Bs[NSTAGE][KSTEP][BSTR];                \
    int tid = threadIdx.x;                                                 \
    int car = tid >> 1, cac = (tid & 1) * 4;                               \
    int cbr = tid >> 5, cbc = (tid & 31) * 4;                              \
    int w = tid >> 5, lane = tid & 31;                                     \
    int m0w = (w >> 2) * 64, n0w = (w & 3) * 32;                           \
    int g = lane >> 2, t = lane & 3;                                       \
    int a_row = m0w + (lane & 7) + ((lane >> 3) & 1) * 8;                  \
    int a_col = (lane >> 4) * 4;                                           \
    float acc[4][4][4];                                                    \
    _Pragma("unroll")                                                      \
    for (int mi = 0; mi < 4; mi++)                                         \
        _Pragma("unroll")                                                  \
        for (int ni = 0; ni < 4; ni++)                                     \
            _Pragma("unroll")                                              \
            for (int j = 0; j < 4; j++) acc[mi][ni][j] = 0.f;

#define PIPE_ISSUE(s, k0, pz, pa)                                          \
    cp16(smem_u32(&As[s][car][cac]), asrc + (k0), ((pz) & (pa)));          \
    cp16(smem_u32(&Bs[s][cbr][cbc]), bsrc + (size_t)((k0) + cbr) * ldb, (pz)); \
    cp_commit();

#define PIPE_LOOP(FRAG, pa)                                                \
    PIPE_ISSUE(0, 0, 16, pa);                                              \
    PIPE_ISSUE(1, KSTEP, 16, pa);                                          \
    PIPE_ISSUE(2, 2 * KSTEP, 16, pa);                                      \
    for (int kb = 0; kb < nkb; kb++) {                                     \
        cp_wait2();                                                        \
        __syncthreads();                                                   \
        int k3 = (kb + 3) * KSTEP;                                         \
        int s3 = (kb + 3) & 3;                                             \
        int pz = (kb + 3 < nkb) ? 16 : 0;                                  \
        PIPE_ISSUE(s3, k3, pz, pa);                                        \
        FRAG(As[kb & 3], Bs[kb & 3], acc, a_row, a_col, n0w, g, t);        \
    }

// ---------------- QKV (tf32x3, fp32-accurate): head-scatter epilogue ----------------
__global__ __launch_bounds__(256, 2) void qkv_x3_kernel(
    const float* __restrict__ A,
    const float* __restrict__ W0, const float* __restrict__ W1, const float* __restrict__ W2,
    const float* __restrict__ b0, const float* __restrict__ b1, const float* __restrict__ b2,
    float* __restrict__ C0, float* __restrict__ C1, float* __restrict__ C2)
{
    int which = blockIdx.z;
    const float* B    = which == 0 ? W0 : (which == 1 ? W1 : W2);
    const float* bias = which == 0 ? b0 : (which == 1 ? b1 : b2);
    float* C          = which == 0 ? C0 : (which == 1 ? C1 : C2);
    float scale       = which == 0 ? 0.125f : 1.0f;
    int m0 = blockIdx.y * TBM;
    int n0 = blockIdx.x * TBN;

    PIPE_DECLS();
    const float* asrc = A + (size_t)(m0 + car) * DM + cac;
    const float* bsrc = B + n0 + cbc;
    const int ldb = DM;
    const int nkb = DM / KSTEP;

    PIPE_LOOP(frag_x3, 16);

#pragma unroll
    for (int mi = 0; mi < 4; mi++) {
#pragma unroll
        for (int ni = 0; ni < 4; ni++) {
            int col = n0 + n0w + ni * 8 + 2 * t;
            float bv0 = bias[col], bv1 = bias[col + 1];
#pragma unroll
            for (int half = 0; half < 2; half++) {
                int row = m0 + m0w + mi * 16 + g + half * 8;
                float v0 = (acc[mi][ni][half * 2 + 0] + bv0) * scale;
                float v1 = (acc[mi][ni][half * 2 + 1] + bv1) * scale;
                C[((size_t)(col >> 6) * SEQ + row) * 64 + (col & 63)]       = v0;
                C[((size_t)((col + 1) >> 6) * SEQ + row) * 64 + ((col + 1) & 63)] = v1;
            }
        }
    }
}

// ---------------- split-K partial GEMM (x3): raw partials ----------------
__global__ __launch_bounds__(256, 2) void gemm_x3_partK(
    const float* __restrict__ A, const float* __restrict__ B,
    float* __restrict__ P, int K)
{
    int z = blockIdx.z;
    int KH = K / 2;
    int m0 = blockIdx.y * TBM;
    int n0 = blockIdx.x * TBN;

    PIPE_DECLS();
    const float* asrc = A + (size_t)(m0 + car) * K + z * KH + cac;
    const float* bsrc = B + (size_t)z * KH * DM + n0 + cbc;
    const int ldb = DM;
    const int nkb = KH / KSTEP;

    PIPE_LOOP(frag_x3, 16);

    float* P_ = P + (size_t)z * SEQ * DM;
#pragma unroll
    for (int mi = 0; mi < 4; mi++) {
#pragma unroll
        for (int ni = 0; ni < 4; ni++) {
            int col = n0 + n0w + ni * 8 + 2 * t;
#pragma unroll
            for (int half = 0; half < 2; half++) {
                int row = m0 + m0w + mi * 16 + g + half * 8;
                size_t idx = (size_t)row * DM + col;
                P_[idx]     = acc[mi][ni][half * 2 + 0];
                P_[idx + 1] = acc[mi][ni][half * 2 + 1];
            }
        }
    }
}

// ---------------- split-K partial GEMM (rn): raw partials ----------------
__global__ __launch_bounds__(256, 2) void gemm_rn_partK(
    const float* __restrict__ A, const float* __restrict__ B,
    float* __restrict__ P, int K)
{
    int z = blockIdx.z;
    int KH = K / 2;
    int m0 = blockIdx.y * TBM;
    int n0 = blockIdx.x * TBN;

    PIPE_DECLS();
    const float* asrc = A + (size_t)(m0 + car) * K + z * KH + cac;
    const float* bsrc = B + (size_t)z * KH * DM + n0 + cbc;
    const int ldb = DM;
    const int nkb = KH / KSTEP;

    PIPE_LOOP(frag_rn, 16);

    float* P_ = P + (size_t)z * SEQ * DM;
#pragma unroll
    for (int mi = 0; mi < 4; mi++) {
#pragma unroll
        for (int ni = 0; ni < 4; ni++) {
            int col = n0 + n0w + ni * 8 + 2 * t;
#pragma unroll
            for (int half = 0; half < 2; half++) {
                int row = m0 + m0w + mi * 16 + g + half * 8;
                size_t idx = (size_t)row * DM + col;
                P_[idx]     = acc[mi][ni][half * 2 + 0];
                P_[idx + 1] = acc[mi][ni][half * 2 + 1];
            }
        }
    }
}

// ---------------- reduce split-K partials: C = p0 + p1 + bias + R ----------------
__global__ __launch_bounds__(192) void reduce2_kernel(
    const float* __restrict__ P, const float* __restrict__ bias,
    const float* __restrict__ R, float* __restrict__ C)
{
    int row = blockIdx.x;
    int i = threadIdx.x * 4;
    size_t idx = (size_t)row * DM + i;
    float4 p0 = *(const float4*)&P[idx];
    float4 p1 = *(const float4*)&P[(size_t)SEQ * DM + idx];
    float4 b  = *(const float4*)&bias[i];
    float4 r  = *(const float4*)&R[idx];
    float4 v;
    v.x = p0.x + p1.x + b.x + r.x;
    v.y = p0.y + p1.y + b.y + r.y;
    v.z = p0.z + p1.z + b.z + r.z;
    v.w = p0.w + p1.w + b.w + r.w;
    *(float4*)&C[idx] = v;
}

// ---------------- MoE GEMM 1 (tf32): gather + GELU, rounded output ----------------
__global__ __launch_bounds__(256, 2) void moe_gemm1_kernel(
    const float* __restrict__ X, const float* __restrict__ W1,
    const float* __restrict__ b1)
{
    int e = blockIdx.z;
    int M = g_cnt[e];
    int m0 = blockIdx.y * TBM;
    if (m0 >= M) return;
    const float* B = W1 + (size_t)e * DM * FF;
    const float* bias = b1 + (size_t)e * FF;
    float* C = g_h + (size_t)e * CAP * FF;
    const int* tl = g_tok + e * CAP;
    int n0 = blockIdx.x * TBN;

    PIPE_DECLS();
    int garow = m0 + car;
    int trow = (garow < M) ? tl[garow] : 0;
    int pa = (garow < M) ? 16 : 0;
    const float* asrc = X + (size_t)trow * DM + cac;
    const float* bsrc = B + n0 + cbc;
    const int ldb = FF;
    const int nkb = DM / KSTEP;

    PIPE_LOOP(frag_rn, pa);

#pragma unroll
    for (int mi = 0; mi < 4; mi++) {
#pragma unroll
        for (int ni = 0; ni < 4; ni++) {
            int col = n0 + n0w + ni * 8 + 2 * t;
            float bv0 = bias[col], bv1 = bias[col + 1];
#pragma unroll
            for (int half = 0; half < 2; half++) {
                int row = m0 + m0w + mi * 16 + g + half * 8;
                if (row >= M) continue;
                float v0 = acc[mi][ni][half * 2 + 0] + bv0;
                float v1 = acc[mi][ni][half * 2 + 1] + bv1;
                v0 = 0.5f * v0 * (1.f + erff(v0 * 0.70710678118654752f));
                v1 = 0.5f * v1 * (1.f + erff(v1 * 0.70710678118654752f));
                // store tf32-rounded (bit-identical to f2tf at GEMM2 load)
                C[(size_t)row * FF + col]     = f2tff(v0);
                C[(size_t)row * FF + col + 1] = f2tff(v1);
            }
        }
    }
}

// ---------------- MoE GEMM 2 (tf32): * gate weight ----------------
__global__ __launch_bounds__(256, 2) void moe_gemm2_kernel(
    const float* __restrict__ W2, const float* __restrict__ b2)
{
    int e = blockIdx.z;
    int M = g_cnt[e];
    int m0 = blockIdx.y * TBM;
    if (m0 >= M) return;
    const float* Ae = g_h + (size_t)e * CAP * FF;
    const float* B = W2 + (size_t)e * FF * DM;
    const float* bias = b2 + (size_t)e * DM;
    const float* wl = g_wl + e * CAP;
    float* C = g_eo + (size_t)e * CAP * DM;
    int n0 = blockIdx.x * TBN;

    PIPE_DECLS();
    int pa = (m0 + car < M) ? 16 : 0;
    const float* asrc = Ae + (size_t)(m0 + car) * FF + cac;
    const float* bsrc = B + n0 + cbc;
    const int ldb = DM;
    const int nkb = FF / KSTEP;

    PIPE_LOOP(frag_rn, pa);

#pragma unroll
    for (int mi = 0; mi < 4; mi++) {
#pragma unroll
        for (int ni = 0; ni < 4; ni++) {
            int col = n0 + n0w + ni * 8 + 2 * t;
            float bv0 = bias[col], bv1 = bias[col + 1];
#pragma unroll
            for (int half = 0; half < 2; half++) {
                int row = m0 + m0w + mi * 16 + g + half * 8;
                if (row >= M) continue;
                float wv = wl[row];
                C[(size_t)row * DM + col]     = (acc[mi][ni][half * 2 + 0] + bv0) * wv;
                C[(size_t)row * DM + col + 1] = (acc[mi][ni][half * 2 + 1] + bv1) * wv;
            }
        }
    }
}

// ---------------- fused sliding-window attention ----------------
#define APAD 68
__global__ __launch_bounds__(256) void attn_kernel(float* __restrict__ out)
{
    __shared__ float Qs[64][APAD];
    __shared__ float Ks[32][APAD];
    __shared__ float Vs[32][APAD];
    __shared__ float Ss[64][33];
    __shared__ float mS[64], lS[64], cS[64];

    int h = blockIdx.y;
    int q0 = blockIdx.x * 64;
    int tid = threadIdx.x;
    int q = tid & 63;
    int kg = tid >> 6;
    int dp = tid >> 6;

    const float* qhead = g_q + (size_t)h * SEQ * DH;
    const float* khead = g_k + (size_t)h * SEQ * DH;
    const float* vhead = g_v + (size_t)h * SEQ * DH;

#pragma unroll
    for (int i = 0; i < 4; i++) {
        int idx = tid + i * 256;
        int r = idx >> 4;
        int c = (idx & 15) << 2;
        float4 v = *(const float4*)&qhead[(size_t)(q0 + r) * DH + c];
        *(float4*)&Qs[r][c] = v;
    }
    if (tid < 64) { mS[tid] = -1e9f; lS[tid] = 0.f; }

    float acc[16];
#pragma unroll
    for (int i = 0; i < 16; i++) acc[i] = 0.f;
    __syncthreads();

    for (int kt = 0; kt < 18; kt++) {
        int kbase = q0 - 256 + kt * 32;
        if (kbase + 31 < 0 || kbase >= SEQ) continue;

#pragma unroll
        for (int i = 0; i < 2; i++) {
            int idx = tid + i * 256;
            int r = idx >> 4;
            int c = (idx & 15) << 2;
            int kpos = kbase + r;
            float4 kv = make_float4(0.f, 0.f, 0.f, 0.f);
            float4 vv = kv;
            if (kpos >= 0 && kpos < SEQ) {
                kv = *(const float4*)&khead[(size_t)kpos * DH + c];
                vv = *(const float4*)&vhead[(size_t)kpos * DH + c];
            }
            *(float4*)&Ks[r][c] = kv;
            *(float4*)&Vs[r][c] = vv;
        }
        __syncthreads();

        float s[8];
#pragma unroll
        for (int j = 0; j < 8; j++) s[j] = 0.f;
#pragma unroll
        for (int d = 0; d < 64; d += 4) {
            float4 q4 = *(const float4*)&Qs[q][d];
#pragma unroll
            for (int j = 0; j < 8; j++) {
                float4 k4 = *(const float4*)&Ks[kg * 8 + j][d];
                s[j] += q4.x * k4.x + q4.y * k4.y + q4.z * k4.z + q4.w * k4.w;
            }
        }
        int qpos = q0 + q;
#pragma unroll
        for (int j = 0; j < 8; j++) {
            int kpos = kbase + kg * 8 + j;
            bool valid = (kpos >= 0) && (kpos < SEQ) &&
                         (kpos >= qpos - WIN) && (kpos <= qpos + WIN);
            Ss[q][kg * 8 + j] = valid ? s[j] : -1e9f;
        }
        __syncthreads();

        if (tid < 64) {
            int r = tid;
            float mold = mS[r];
            float tmax = -1e9f;
#pragma unroll
            for (int kk = 0; kk < 32; kk++) tmax = fmaxf(tmax, Ss[r][kk]);
            float mnew = fmaxf(mold, tmax);
            float corr = __expf(mold - mnew);
            float sum = 0.f;
#pragma unroll
            for (int kk = 0; kk < 32; kk++) {
                float p = __expf(Ss[r][kk] - mnew);
                Ss[r][kk] = p;
                sum += p;
            }
            lS[r] = lS[r] * corr + sum;
            mS[r] = mnew;
            cS[r] = corr;
        }
        __syncthreads();

        float corr = cS[q];
#pragma unroll
        for (int i = 0; i < 16; i++) acc[i] *= corr;
#pragma unroll
        for (int kk = 0; kk < 32; kk++) {
            float p = Ss[q][kk];
#pragma unroll
            for (int i4 = 0; i4 < 4; i4++) {
                float4 v4 = *(const float4*)&Vs[kk][dp * 16 + i4 * 4];
                acc[i4 * 4 + 0] += p * v4.x;
                acc[i4 * 4 + 1] += p * v4.y;
                acc[i4 * 4 + 2] += p * v4.z;
                acc[i4 * 4 + 3] += p * v4.w;
            }
        }
        __syncthreads();
    }

    float inv = 1.f / lS[q];
    float* o = out + (size_t)(q0 + q) * DM + h * DH + dp * 16;
#pragma unroll
    for (int i4 = 0; i4 < 4; i4++) {
        float4 v;
        v.x = acc[i4 * 4 + 0] * inv;
        v.y = acc[i4 * 4 + 1] * inv;
        v.z = acc[i4 * 4 + 2] * inv;
        v.w = acc[i4 * 4 + 3] * inv;
        *(float4*)&o[i4 * 4] = v;
    }
}

// ---------------- layer norm (row-wise); optional tf32-rounded copy ----------------
__global__ __launch_bounds__(256) void ln_kernel(
    const float* __restrict__ in, const float* __restrict__ g,
    const float* __restrict__ b, float* __restrict__ out,
    float* __restrict__ out_r)
{
    __shared__ float rs[8], rs2[8];
    int row = blockIdx.x;
    int tid = threadIdx.x;
    const float* x = in + (size_t)row * DM;
    float vals[3];
    float s = 0.f, s2 = 0.f;
#pragma unroll
    for (int i = 0; i < 3; i++) {
        float v = x[tid + i * 256];
        vals[i] = v;
        s += v;
        s2 += v * v;
    }
    int lane = tid & 31, w = tid >> 5;
#pragma unroll
    for (int o = 16; o; o >>= 1) {
        s += __shfl_down_sync(0xffffffffu, s, o);
        s2 += __shfl_down_sync(0xffffffffu, s2, o);
    }
    if (lane == 0) { rs[w] = s; rs2[w] = s2; }
    __syncthreads();
    if (tid == 0) {
        float a = 0.f, c = 0.f;
#pragma unroll
        for (int i = 0; i < 8; i++) { a += rs[i]; c += rs2[i]; }
        rs[0] = a;
        rs2[0] = c;
    }
    __syncthreads();
    float mean = rs[0] * (1.f / DM);
    float var = rs2[0] * (1.f / DM) - mean * mean;
    float rstd = rsqrtf(var + 1e-5f);
    float* o = out + (size_t)row * DM;
#pragma unroll
    for (int i = 0; i < 3; i++) {
        int col = tid + i * 256;
        float v = (vals[i] - mean) * rstd * g[col] + b[col];
        o[col] = v;
        if (out_r) out_r[(size_t)row * DM + col] = f2tff(v);
    }
}

// ---------------- gating: logits, top-2, softmax, expert lists ----------------
__global__ __launch_bounds__(256) void gating_kernel(
    const float* __restrict__ x1, const float* __restrict__ gW,
    const float* __restrict__ gb, float* __restrict__ gate_out)
{
    __shared__ float xs[DM];
    __shared__ float lg[8];
    int row = blockIdx.x;
    int tid = threadIdx.x;
    for (int i = tid; i < DM; i += 256) xs[i] = x1[(size_t)row * DM + i];
    __syncthreads();
    int w = tid >> 5, lane = tid & 31;
    if (w < NE) {
        float p = 0.f;
        for (int d = lane; d < DM; d += 32) p += xs[d] * gW[d * NE + w];
#pragma unroll
        for (int o = 16; o; o >>= 1) p += __shfl_down_sync(0xffffffffu, p, o);
        if (lane == 0) lg[w] = p + gb[w];
    }
    __syncthreads();
    if (tid == 0) {
        int e1 = 0;
        float v1 = lg[0];
        for (int e = 1; e < NE; e++)
            if (lg[e] > v1) { v1 = lg[e]; e1 = e; }
        int e2 = -1;
        float v2 = -1e30f;
        for (int e = 0; e < NE; e++) {
            if (e == e1) continue;
            if (lg[e] > v2) { v2 = lg[e]; e2 = e; }
        }
        float z = expf(v2 - v1);
        float w1 = 1.f / (1.f + z);
        float w2 = z / (1.f + z);
        float* go = gate_out + (size_t)row * NE;
#pragma unroll
        for (int e = 0; e < NE; e++) go[e] = 0.f;
        go[e1] = w1;
        go[e2] = w2;
        int s1 = atomicAdd(&g_cnt[e1], 1);
        g_tok[e1 * CAP + s1] = row;
        g_wl[e1 * CAP + s1] = w1;
        g_pos[row * 2 + 0] = e1 * CAP + s1;
        int s2 = atomicAdd(&g_cnt[e2], 1);
        g_tok[e2 * CAP + s2] = row;
        g_wl[e2 * CAP + s2] = w2;
        g_pos[row * 2 + 1] = e2 * CAP + s2;
    }
}

// ---------------- combine two expert outputs per token (rounded for Wd-A) ----------------
__global__ __launch_bounds__(192) void combine_kernel()
{
    int tk = blockIdx.x;
    int p0 = g_pos[tk * 2 + 0];
    int p1 = g_pos[tk * 2 + 1];
    const float* a = g_eo + (size_t)p0 * DM;
    const float* b = g_eo + (size_t)p1 * DM;
    float* o = g_moe + (size_t)tk * DM;
    int i = threadIdx.x * 4;
    float4 av = *(const float4*)&a[i];
    float4 bv = *(const float4*)&b[i];
    float4 v;
    v.x = f2tff(av.x + bv.x);
    v.y = f2tff(av.y + bv.y);
    v.z = f2tff(av.z + bv.z);
    v.w = f2tff(av.w + bv.w);
    *(float4*)&o[i] = v;
}

// ---------------- launch ----------------
extern "C" void kernel_launch(void* const* d_in, const int* in_sizes, int n_in,
                              void* d_out, int out_size)
{
    (void)in_sizes; (void)n_in; (void)out_size;
    const float* x     = (const float*)d_in[0];
    const float* Wq    = (const float*)d_in[1];
    const float* bq    = (const float*)d_in[2];
    const float* Wk    = (const float*)d_in[3];
    const float* bk    = (const float*)d_in[4];
    const float* Wv    = (const float*)d_in[5];
    const float* bv    = (const float*)d_in[6];
    const float* Wo    = (const float*)d_in[7];
    const float* bo    = (const float*)d_in[8];
    const float* ln1g  = (const float*)d_in[9];
    const float* ln1b  = (const float*)d_in[10];
    const float* gateW = (const float*)d_in[11];
    const float* gateb = (const float*)d_in[12];
    const float* W1e   = (const float*)d_in[13];
    const float* b1e   = (const float*)d_in[14];
    const float* W2e   = (const float*)d_in[15];
    const float* b2e   = (const float*)d_in[16];
    const float* Wd    = (const float*)d_in[17];
    const float* bd    = (const float*)d_in[18];
    const float* ln2g  = (const float*)d_in[19];
    const float* ln2b  = (const float*)d_in[20];

    float* out = (float*)d_out;
    float* gate_out = out + (size_t)SEQ * DM;

    float *pq, *pk, *pv, *pattno, *ptmp, *px1, *px1r, *pmoe, *ppart;
    cudaGetSymbolAddress((void**)&pq, g_q);
    cudaGetSymbolAddress((void**)&pk, g_k);
    cudaGetSymbolAddress((void**)&pv, g_v);
    cudaGetSymbolAddress((void**)&pattno, g_attno);
    cudaGetSymbolAddress((void**)&ptmp, g_tmp);
    cudaGetSymbolAddress((void**)&px1, g_x1);
    cudaGetSymbolAddress((void**)&px1r, g_x1r);
    cudaGetSymbolAddress((void**)&pmoe, g_moe);
    cudaGetSymbolAddress((void**)&ppart, g_part);

    reset_kernel<<<1, 32>>>();

    // QKV projections (tf32x3 ~ fp32 accuracy; q pre-scaled by 1/sqrt(64))
    qkv_x3_kernel<<<dim3(DM / TBN, SEQ / TBM, 3), 256>>>(
        x, Wq, Wk, Wv, bq, bk, bv, pq, pk, pv);

    // sliding-window attention (fp32)
    attn_kernel<<<dim3(SEQ / 64, NH), 256>>>(pattno);

    // Wo projection (tf32x3, split-K2) + reduce(+bias+residual) -> LN1 -> x1 (+rounded copy)
    gemm_x3_partK<<<dim3(DM / TBN, SEQ / TBM, 2), 256>>>(pattno, Wo, ppart, DM);
    reduce2_kernel<<<SEQ, 192>>>(ppart, bo, x, ptmp);
    ln_kernel<<<SEQ, 256>>>(ptmp, ln1g, ln1b, px1, px1r);

    // gating (fp32-exact; writes gate_weights output + expert lists)
    gating_kernel<<<SEQ, 256>>>(px1, gateW, gateb, gate_out);

    // MoE expert FFN (tf32 tensor cores, grouped sparse top-2; A operands pre-rounded)
    moe_gemm1_kernel<<<dim3(FF / TBN, CAP / TBM, NE), 256>>>(px1r, W1e, b1e);
    moe_gemm2_kernel<<<dim3(DM / TBN, CAP / TBM, NE), 256>>>(W2e, b2e);
    combine_kernel<<<SEQ, 192>>>();

    // Wd projection (tf32, split-K2) + reduce(+bias+residual x1) -> LN2 -> layer_output
    gemm_rn_partK<<<dim3(DM / TBN, SEQ / TBM, 2), 256>>>(pmoe, Wd, ppart, DM);
    reduce2_kernel<<<SEQ, 192>>>(ppart, bd, px1, ptmp);
    ln_kernel<<<SEQ, 256>>>(ptmp, ln2g, ln2b, out, nullptr);
}